// round 5
// baseline (speedup 1.0000x reference)
#include <cuda_runtime.h>
#include <math.h>
#include <stdint.h>

#define T_STEPS 256
#define B_SZ 64
#define D_SZ 2048
#define BD (B_SZ * D_SZ)                 // 131072
#define TBD (T_STEPS * BD)               // 33554432

// ---------------- device scratch (no allocations allowed) ----------------
__device__ float g_xwx[TBD];             // x @ W_x^T + b
__device__ float g_gate[TBD];            // sigmoid(x @ W_gate^T)
__device__ float g_hbuf[(T_STEPS + 1) * BD]; // fallback h chain if out only holds `output`
__device__ float g_u[D_SZ];
__device__ float g_v[D_SZ];
__device__ float g_w[D_SZ];
__device__ float g_scale;

// ---------------- threefry2x32 (JAX partitionable mode) ----------------
__device__ __forceinline__ uint32_t rotl32(uint32_t x, int n) {
    return (x << n) | (x >> (32 - n));
}

#define TF_ROUND(x0, x1, r) do { x0 += x1; x1 = rotl32(x1, r); x1 ^= x0; } while (0)
#define TF_G_A(x0, x1) do { TF_ROUND(x0,x1,13); TF_ROUND(x0,x1,15); TF_ROUND(x0,x1,26); TF_ROUND(x0,x1,6); } while (0)
#define TF_G_B(x0, x1) do { TF_ROUND(x0,x1,17); TF_ROUND(x0,x1,29); TF_ROUND(x0,x1,16); TF_ROUND(x0,x1,24); } while (0)

// Full 20-round threefry2x32 with key (k1=0, k2=42); returns o0 ^ o1
// (partitionable path, bit_width=32: bits = bits1 ^ bits2).
__device__ __forceinline__ uint32_t threefry_part_bits(uint32_t cnt_hi, uint32_t cnt_lo) {
    const uint32_t ks0 = 0u, ks1 = 42u;
    const uint32_t ks2 = 0x1BD11BDAu ^ ks0 ^ ks1;
    uint32_t x0 = cnt_hi + ks0;
    uint32_t x1 = cnt_lo + ks1;
    TF_G_A(x0, x1); x0 += ks1; x1 += ks2 + 1u;
    TF_G_B(x0, x1); x0 += ks2; x1 += ks0 + 2u;
    TF_G_A(x0, x1); x0 += ks0; x1 += ks1 + 3u;
    TF_G_B(x0, x1); x0 += ks1; x1 += ks2 + 4u;
    TF_G_A(x0, x1); x0 += ks2; x1 += ks0 + 5u;
    return x0 ^ x1;
}

__device__ __forceinline__ float bits_to_normal(uint32_t bits) {
    // jax uniform: f = bitcast((bits>>9)|0x3f800000) - 1  in [0,1)
    float f = __uint_as_float((bits >> 9) | 0x3f800000u) - 1.0f;
    const float lo = -0.99999994f;       // nextafterf(-1,0)
    const float span = 2.0f;             // (1.0f - lo) rounds to 2.0f in fp32
    float u = fmaf(f, span, lo);
    u = fmaxf(lo, u);
    return 1.41421356237f * erfinvf(u);  // sqrt(2)*erfinv
}

// u0 = normal(key(42), (2048,)); u0 /= ||u0||
__global__ void k_init_u(float* __restrict__ u_out) {
    __shared__ float red[1024];
    __shared__ float inv;
    int i = threadIdx.x;  // 0..1023, handles elements i and i+1024

    // partitionable: counter for element e is the 64-bit value e -> (hi=0, lo=e)
    float n0 = bits_to_normal(threefry_part_bits(0u, (uint32_t)i));
    float n1 = bits_to_normal(threefry_part_bits(0u, (uint32_t)(i + 1024)));

    red[i] = n0 * n0 + n1 * n1;
    __syncthreads();
    for (int s = 512; s > 0; s >>= 1) {
        if (i < s) red[i] += red[i + s];
        __syncthreads();
    }
    if (i == 0) inv = 1.0f / sqrtf(red[0]);   // no EPS on the initial normalize
    __syncthreads();
    u_out[i] = n0 * inv;
    u_out[i + 1024] = n1 * inv;
}

// v_raw[j] = sum_i W[i,j] * u[i]   (W^T @ u), coalesced over j
__global__ void __launch_bounds__(256) k_mvT(const float* __restrict__ W,
                                             const float* __restrict__ u,
                                             float* __restrict__ v) {
    __shared__ float part[2][128];
    int t = threadIdx.x;
    int jl = t & 127, half = t >> 7;
    int j = blockIdx.x * 128 + jl;
    int i0 = half * 1024;
    float s = 0.0f;
#pragma unroll 8
    for (int i = 0; i < 1024; i++)
        s = fmaf(W[(size_t)(i0 + i) * D_SZ + j], u[i0 + i], s);
    part[half][jl] = s;
    __syncthreads();
    if (t < 128) v[blockIdx.x * 128 + t] = part[0][t] + part[1][t];
}

// o[r] = dot(W[r,:], v)  — one warp per row
__global__ void __launch_bounds__(256) k_mv(const float* __restrict__ W,
                                            const float* __restrict__ v,
                                            float* __restrict__ o) {
    int gw = (blockIdx.x * blockDim.x + threadIdx.x) >> 5;
    int lane = threadIdx.x & 31;
    const float* row = W + (size_t)gw * D_SZ;
    float s = 0.0f;
#pragma unroll 8
    for (int k = lane; k < D_SZ; k += 32) s = fmaf(row[k], v[k], s);
#pragma unroll
    for (int off = 16; off > 0; off >>= 1)
        s += __shfl_xor_sync(0xffffffffu, s, off);
    if (lane == 0) o[gw] = s;
}

// vec /= (||vec|| + EPS)
__global__ void k_norm(float* __restrict__ v) {
    __shared__ float red[1024];
    __shared__ float inv;
    int i = threadIdx.x;
    float a = v[i], b = v[i + 1024];
    red[i] = a * a + b * b;
    __syncthreads();
    for (int s = 512; s > 0; s >>= 1) {
        if (i < s) red[i] += red[i + s];
        __syncthreads();
    }
    if (i == 0) inv = 1.0f / (sqrtf(red[0]) + 1e-8f);
    __syncthreads();
    v[i] = a * inv;
    v[i + 1024] = b * inv;
}

// scale = 0.99 / (|u·w| + EPS)
__global__ void k_sigma(const float* __restrict__ u, const float* __restrict__ w,
                        float* __restrict__ scale) {
    __shared__ float red[1024];
    int i = threadIdx.x;
    red[i] = u[i] * w[i] + u[i + 1024] * w[i + 1024];
    __syncthreads();
    for (int s = 512; s > 0; s >>= 1) {
        if (i < s) red[i] += red[i + s];
        __syncthreads();
    }
    if (i == 0) scale[0] = 0.99f / (fabsf(red[0]) + 1e-8f);
}

// ---------------- big SGEMM: C[m,n] = sum_k A[m,k] * B[n,k], epilogue bias / sigmoid ----
#define BM 128
#define BN 128
#define BK 16

__global__ void __launch_bounds__(256) sgemm_kernel(const float* __restrict__ A,
                                                    const float* __restrict__ B,
                                                    const float* __restrict__ bias,
                                                    float* __restrict__ C,
                                                    int mode /*0: +bias, 1: sigmoid*/) {
    __shared__ float As[BK][BM + 4];
    __shared__ float Bs[BK][BN + 4];
    const int K = D_SZ, N = D_SZ;
    int t = threadIdx.x;
    int m0 = blockIdx.y * BM, n0 = blockIdx.x * BN;
    int tx = t & 15, ty = t >> 4;
    int lr = t >> 2;           // 0..63
    int lc = (t & 3) * 4;      // 0,4,8,12

    float acc[8][8];
#pragma unroll
    for (int i = 0; i < 8; i++)
#pragma unroll
        for (int j = 0; j < 8; j++) acc[i][j] = 0.0f;

    for (int k0 = 0; k0 < K; k0 += BK) {
#pragma unroll
        for (int rr = 0; rr < 2; rr++) {
            int row = lr + rr * 64;
            float4 av = *(const float4*)&A[(size_t)(m0 + row) * K + k0 + lc];
            As[lc + 0][row] = av.x; As[lc + 1][row] = av.y;
            As[lc + 2][row] = av.z; As[lc + 3][row] = av.w;
            float4 bv = *(const float4*)&B[(size_t)(n0 + row) * K + k0 + lc];
            Bs[lc + 0][row] = bv.x; Bs[lc + 1][row] = bv.y;
            Bs[lc + 2][row] = bv.z; Bs[lc + 3][row] = bv.w;
        }
        __syncthreads();
#pragma unroll
        for (int k = 0; k < BK; k++) {
            float ra[8], rb[8];
            *(float4*)&ra[0] = *(const float4*)&As[k][ty * 8];
            *(float4*)&ra[4] = *(const float4*)&As[k][ty * 8 + 4];
            *(float4*)&rb[0] = *(const float4*)&Bs[k][tx * 8];
            *(float4*)&rb[4] = *(const float4*)&Bs[k][tx * 8 + 4];
#pragma unroll
            for (int i = 0; i < 8; i++)
#pragma unroll
                for (int j = 0; j < 8; j++)
                    acc[i][j] = fmaf(ra[i], rb[j], acc[i][j]);
        }
        __syncthreads();
    }

#pragma unroll
    for (int i = 0; i < 8; i++) {
        int m = m0 + ty * 8 + i;
#pragma unroll
        for (int j = 0; j < 8; j++) {
            int n = n0 + tx * 8 + j;
            float v = acc[i][j];
            if (mode == 0) v += bias[n];
            else           v = 1.0f / (1.0f + expf(-v));
            C[(size_t)m * N + n] = v;
        }
    }
}

// ---------------- recurrence step: Rh = h_prev @ W_h^T (scaled), fused epilogue ----------
#define TE 8   // output features per block; grid = 2048/8 = 256 blocks

__global__ void __launch_bounds__(256) step_kernel(const float* __restrict__ Wh,
                                                   const float* __restrict__ xwx_t,
                                                   const float* __restrict__ gate_t,
                                                   const float* __restrict__ z_t,
                                                   const float* __restrict__ hprev,
                                                   float* __restrict__ hnext,
                                                   float* __restrict__ out_t,
                                                   const float* __restrict__ scale) {
    __shared__ float hs[64 * 68];        // [k][b], padded row 68
    __shared__ float ws[TE * 64];        // [e][k]
    int t = threadIdx.x;
    int e0 = blockIdx.x * TE;
    int b0 = (t & 31) * 2;               // 2 consecutive batch rows
    int el = t >> 5;                     // 0..7

    float acc0 = 0.f, acc1 = 0.f;

    for (int kc = 0; kc < D_SZ; kc += 64) {
#pragma unroll
        for (int i = 0; i < 16; i++) {
            int lin = t + i * 256;
            int b = lin >> 6, k = lin & 63;
            hs[k * 68 + b] = hprev[b * D_SZ + kc + k];
        }
#pragma unroll
        for (int i = 0; i < 2; i++) {
            int lin = t + i * 256;
            int e = lin >> 6, k = lin & 63;
            ws[e * 64 + k] = Wh[(size_t)(e0 + e) * D_SZ + kc + k];
        }
        __syncthreads();
#pragma unroll 16
        for (int k = 0; k < 64; k++) {
            float2 hv = *(const float2*)&hs[k * 68 + b0];
            float wv = ws[el * 64 + k];
            acc0 = fmaf(hv.x, wv, acc0);
            acc1 = fmaf(hv.y, wv, acc1);
        }
        __syncthreads();
    }

    float s = scale[0];
    int e = e0 + el;
    float accs[2] = {acc0, acc1};
#pragma unroll
    for (int j = 0; j < 2; j++) {
        int b = b0 + j;
        int idx = b * D_SZ + e;
        float Rh = accs[j] * s;
        float g = gate_t[idx];
        float pre = xwx_t[idx] + Rh * g;
        float h = tanhf(pre);
        hnext[idx] = h;
        float zz = z_t[idx];
        float sz = zz / (1.0f + expf(-zz));   // silu
        out_t[idx] = h * sz;
    }
}

// ---------------- launch ----------------
extern "C" void kernel_launch(void* const* d_in, const int* in_sizes, int n_in,
                              void* d_out, int out_size) {
    const float* x    = (const float*)d_in[0];
    const float* z    = (const float*)d_in[1];
    const float* h0   = (const float*)d_in[2];
    const float* Wx   = (const float*)d_in[3];
    const float* Wh   = (const float*)d_in[4];
    const float* Wg   = (const float*)d_in[5];
    const float* bias = (const float*)d_in[6];
    float* out = (float*)d_out;

    float *p_u, *p_v, *p_w, *p_scale, *p_xwx, *p_gate, *p_hbuf;
    cudaGetSymbolAddress((void**)&p_u, g_u);
    cudaGetSymbolAddress((void**)&p_v, g_v);
    cudaGetSymbolAddress((void**)&p_w, g_w);
    cudaGetSymbolAddress((void**)&p_scale, g_scale);
    cudaGetSymbolAddress((void**)&p_xwx, g_xwx);
    cudaGetSymbolAddress((void**)&p_gate, g_gate);
    cudaGetSymbolAddress((void**)&p_hbuf, g_hbuf);

    long long need = (long long)TBD + (long long)(T_STEPS + 1) * BD;
    float* out_h = ((long long)out_size >= need) ? (out + TBD) : p_hbuf;

    // --- spectral norm of W_h ---
    k_init_u<<<1, 1024>>>(p_u);
    for (int it = 0; it < 3; it++) {
        k_mvT<<<16, 256>>>(Wh, p_u, p_v);
        k_norm<<<1, 1024>>>(p_v);
        k_mv<<<256, 256>>>(Wh, p_v, p_u);
        k_norm<<<1, 1024>>>(p_u);
    }
    k_mv<<<256, 256>>>(Wh, p_v, p_w);
    k_sigma<<<1, 1024>>>(p_u, p_w, p_scale);

    // --- input projections ---
    dim3 gg(D_SZ / BN, (T_STEPS * B_SZ) / BM);  // (16, 128)
    sgemm_kernel<<<gg, 256>>>(x, Wx, bias, p_xwx, 0);
    sgemm_kernel<<<gg, 256>>>(x, Wg, bias, p_gate, 1);

    // h[0] = h0
    cudaMemcpyAsync(out_h, h0, (size_t)BD * sizeof(float), cudaMemcpyDeviceToDevice);

    // --- sequential recurrence ---
    for (int t = 0; t < T_STEPS; t++) {
        step_kernel<<<D_SZ / TE, 256>>>(Wh,
                                        p_xwx + (size_t)t * BD,
                                        p_gate + (size_t)t * BD,
                                        z + (size_t)t * BD,
                                        out_h + (size_t)t * BD,
                                        out_h + (size_t)(t + 1) * BD,
                                        out + (size_t)t * BD,
                                        p_scale);
    }
}

// round 6
// speedup vs baseline: 1.7267x; 1.7267x over previous
#include <cuda_runtime.h>
#include <cuda_bf16.h>
#include <math.h>
#include <stdint.h>

#define T_STEPS 256
#define B_SZ 64
#define D_SZ 2048
#define BD (B_SZ * D_SZ)                 // 131072
#define TBD (T_STEPS * BD)               // 33554432
#define DD (D_SZ * D_SZ)                 // 4194304

// ---------------- device scratch (no allocations allowed) ----------------
__device__ float g_xwx[TBD];             // x @ W_x^T + b
__device__ float g_gate[TBD];            // sigmoid(x @ W_gate^T)
__device__ float g_hbuf[(T_STEPS + 1) * BD]; // fallback h chain
__device__ float g_u[D_SZ];
__device__ float g_v[D_SZ];
__device__ float g_w[D_SZ];
__device__ float g_scale;

// split-bf16 operands
__device__ __nv_bfloat16 gx_hi[TBD], gx_lo[TBD];
__device__ __nv_bfloat16 gwx_hi[DD], gwx_lo[DD];
__device__ __nv_bfloat16 gwg_hi[DD], gwg_lo[DD];
__device__ __nv_bfloat16 gwh_hi[DD], gwh_lo[DD];
__device__ __nv_bfloat16 gh_hi[2][BD], gh_lo[2][BD];

// ---------------- threefry2x32 (JAX partitionable mode) ----------------
__device__ __forceinline__ uint32_t rotl32(uint32_t x, int n) {
    return (x << n) | (x >> (32 - n));
}
#define TF_ROUND(x0, x1, r) do { x0 += x1; x1 = rotl32(x1, r); x1 ^= x0; } while (0)
#define TF_G_A(x0, x1) do { TF_ROUND(x0,x1,13); TF_ROUND(x0,x1,15); TF_ROUND(x0,x1,26); TF_ROUND(x0,x1,6); } while (0)
#define TF_G_B(x0, x1) do { TF_ROUND(x0,x1,17); TF_ROUND(x0,x1,29); TF_ROUND(x0,x1,16); TF_ROUND(x0,x1,24); } while (0)

__device__ __forceinline__ uint32_t threefry_part_bits(uint32_t cnt_hi, uint32_t cnt_lo) {
    const uint32_t ks0 = 0u, ks1 = 42u;
    const uint32_t ks2 = 0x1BD11BDAu ^ ks0 ^ ks1;
    uint32_t x0 = cnt_hi + ks0;
    uint32_t x1 = cnt_lo + ks1;
    TF_G_A(x0, x1); x0 += ks1; x1 += ks2 + 1u;
    TF_G_B(x0, x1); x0 += ks2; x1 += ks0 + 2u;
    TF_G_A(x0, x1); x0 += ks0; x1 += ks1 + 3u;
    TF_G_B(x0, x1); x0 += ks1; x1 += ks2 + 4u;
    TF_G_A(x0, x1); x0 += ks2; x1 += ks0 + 5u;
    return x0 ^ x1;
}

__device__ __forceinline__ float bits_to_normal(uint32_t bits) {
    float f = __uint_as_float((bits >> 9) | 0x3f800000u) - 1.0f;
    const float lo = -0.99999994f;
    const float span = 2.0f;
    float u = fmaf(f, span, lo);
    u = fmaxf(lo, u);
    return 1.41421356237f * erfinvf(u);
}

__global__ void k_init_u(float* __restrict__ u_out) {
    __shared__ float red[1024];
    __shared__ float inv;
    int i = threadIdx.x;
    float n0 = bits_to_normal(threefry_part_bits(0u, (uint32_t)i));
    float n1 = bits_to_normal(threefry_part_bits(0u, (uint32_t)(i + 1024)));
    red[i] = n0 * n0 + n1 * n1;
    __syncthreads();
    for (int s = 512; s > 0; s >>= 1) {
        if (i < s) red[i] += red[i + s];
        __syncthreads();
    }
    if (i == 0) inv = 1.0f / sqrtf(red[0]);
    __syncthreads();
    u_out[i] = n0 * inv;
    u_out[i + 1024] = n1 * inv;
}

__global__ void __launch_bounds__(256) k_mvT(const float* __restrict__ W,
                                             const float* __restrict__ u,
                                             float* __restrict__ v) {
    __shared__ float part[2][128];
    int t = threadIdx.x;
    int jl = t & 127, half = t >> 7;
    int j = blockIdx.x * 128 + jl;
    int i0 = half * 1024;
    float s = 0.0f;
#pragma unroll 8
    for (int i = 0; i < 1024; i++)
        s = fmaf(W[(size_t)(i0 + i) * D_SZ + j], u[i0 + i], s);
    part[half][jl] = s;
    __syncthreads();
    if (t < 128) v[blockIdx.x * 128 + t] = part[0][t] + part[1][t];
}

__global__ void __launch_bounds__(256) k_mv(const float* __restrict__ W,
                                            const float* __restrict__ v,
                                            float* __restrict__ o) {
    int gw = (blockIdx.x * blockDim.x + threadIdx.x) >> 5;
    int lane = threadIdx.x & 31;
    const float* row = W + (size_t)gw * D_SZ;
    float s = 0.0f;
#pragma unroll 8
    for (int k = lane; k < D_SZ; k += 32) s = fmaf(row[k], v[k], s);
#pragma unroll
    for (int off = 16; off > 0; off >>= 1)
        s += __shfl_xor_sync(0xffffffffu, s, off);
    if (lane == 0) o[gw] = s;
}

__global__ void k_norm(float* __restrict__ v) {
    __shared__ float red[1024];
    __shared__ float inv;
    int i = threadIdx.x;
    float a = v[i], b = v[i + 1024];
    red[i] = a * a + b * b;
    __syncthreads();
    for (int s = 512; s > 0; s >>= 1) {
        if (i < s) red[i] += red[i + s];
        __syncthreads();
    }
    if (i == 0) inv = 1.0f / (sqrtf(red[0]) + 1e-8f);
    __syncthreads();
    v[i] = a * inv;
    v[i + 1024] = b * inv;
}

__global__ void k_sigma(const float* __restrict__ u, const float* __restrict__ w,
                        float* __restrict__ scale) {
    __shared__ float red[1024];
    int i = threadIdx.x;
    red[i] = u[i] * w[i] + u[i + 1024] * w[i + 1024];
    __syncthreads();
    for (int s = 512; s > 0; s >>= 1) {
        if (i < s) red[i] += red[i + s];
        __syncthreads();
    }
    if (i == 0) scale[0] = 0.99f / (fabsf(red[0]) + 1e-8f);
}

// ---------------- fp32 -> (hi, lo) bf16 split ----------------
__global__ void __launch_bounds__(256) k_split(const float* __restrict__ src,
                                               __nv_bfloat16* __restrict__ hi,
                                               __nv_bfloat16* __restrict__ lo) {
    int i = blockIdx.x * blockDim.x + threadIdx.x;  // handles 4 elems
    float4 v = ((const float4*)src)[i];
    union { __nv_bfloat16 b[4]; uint2 u; } ph, pl;
    float vv[4] = {v.x, v.y, v.z, v.w};
#pragma unroll
    for (int j = 0; j < 4; j++) {
        __nv_bfloat16 h = __float2bfloat16(vv[j]);
        ph.b[j] = h;
        pl.b[j] = __float2bfloat16(vv[j] - __bfloat162float(h));
    }
    ((uint2*)hi)[i] = ph.u;
    ((uint2*)lo)[i] = pl.u;
}

// ---------------- mma.sync helper ----------------
__device__ __forceinline__ void mma16816(float* c,
                                         uint32_t a0, uint32_t a1, uint32_t a2, uint32_t a3,
                                         uint32_t b0, uint32_t b1) {
    asm volatile(
        "mma.sync.aligned.m16n8k16.row.col.f32.bf16.bf16.f32 "
        "{%0,%1,%2,%3}, {%4,%5,%6,%7}, {%8,%9}, {%0,%1,%2,%3};\n"
        : "+f"(c[0]), "+f"(c[1]), "+f"(c[2]), "+f"(c[3])
        : "r"(a0), "r"(a1), "r"(a2), "r"(a3), "r"(b0), "r"(b1));
}

// ---------------- big GEMM: C[m,n] = sum_k A[m,k]*B[n,k] (split-bf16, 3 terms) ----------
#define GBM 128
#define GBN 128
#define GBK 32
#define GLDW (GBK + 8)   // 40: stride 20 banks -> conflict-free fragment loads

__global__ void __launch_bounds__(256) mma_gemm(const __nv_bfloat16* __restrict__ Ah,
                                                const __nv_bfloat16* __restrict__ Al,
                                                const __nv_bfloat16* __restrict__ Bh,
                                                const __nv_bfloat16* __restrict__ Bl,
                                                const float* __restrict__ bias,
                                                float* __restrict__ C,
                                                int mode /*0: +bias, 1: sigmoid*/) {
    __shared__ __nv_bfloat16 sAh[GBM][GLDW], sAl[GBM][GLDW];
    __shared__ __nv_bfloat16 sBh[GBN][GLDW], sBl[GBN][GLDW];
    const int K = D_SZ, N = D_SZ;
    int t = threadIdx.x;
    int warp = t >> 5, lane = t & 31;
    int g = lane >> 2, tg = lane & 3;
    int wm = warp >> 2, wn = warp & 3;           // 2 x 4 warp grid
    int m0 = blockIdx.y * GBM, n0 = blockIdx.x * GBN;

    float acc[4][4][4];
#pragma unroll
    for (int mi = 0; mi < 4; mi++)
#pragma unroll
        for (int ni = 0; ni < 4; ni++)
#pragma unroll
            for (int j = 0; j < 4; j++) acc[mi][ni][j] = 0.0f;

    for (int kt = 0; kt < K / GBK; kt++) {
        int k0 = kt * GBK;
        // load 4 tiles: each 128x32 bf16 = 512 uint4; 2 per thread per tile
#pragma unroll
        for (int i = 0; i < 2; i++) {
            int lin = t + i * 256;
            int r = lin >> 2, c = (lin & 3) * 8;
            *(uint4*)&sAh[r][c] = *(const uint4*)&Ah[(size_t)(m0 + r) * K + k0 + c];
            *(uint4*)&sAl[r][c] = *(const uint4*)&Al[(size_t)(m0 + r) * K + k0 + c];
            *(uint4*)&sBh[r][c] = *(const uint4*)&Bh[(size_t)(n0 + r) * K + k0 + c];
            *(uint4*)&sBl[r][c] = *(const uint4*)&Bl[(size_t)(n0 + r) * K + k0 + c];
        }
        __syncthreads();
#pragma unroll
        for (int ks = 0; ks < 2; ks++) {
            int kb = ks * 16;
            uint32_t ah[4][4], al[4][4];
#pragma unroll
            for (int mi = 0; mi < 4; mi++) {
                int rb = wm * 64 + mi * 16;
                ah[mi][0] = *(const uint32_t*)&sAh[rb + g][kb + tg * 2];
                ah[mi][1] = *(const uint32_t*)&sAh[rb + g + 8][kb + tg * 2];
                ah[mi][2] = *(const uint32_t*)&sAh[rb + g][kb + tg * 2 + 8];
                ah[mi][3] = *(const uint32_t*)&sAh[rb + g + 8][kb + tg * 2 + 8];
                al[mi][0] = *(const uint32_t*)&sAl[rb + g][kb + tg * 2];
                al[mi][1] = *(const uint32_t*)&sAl[rb + g + 8][kb + tg * 2];
                al[mi][2] = *(const uint32_t*)&sAl[rb + g][kb + tg * 2 + 8];
                al[mi][3] = *(const uint32_t*)&sAl[rb + g + 8][kb + tg * 2 + 8];
            }
#pragma unroll
            for (int ni = 0; ni < 4; ni++) {
                int nb = wn * 32 + ni * 8 + g;
                uint32_t bh0 = *(const uint32_t*)&sBh[nb][kb + tg * 2];
                uint32_t bh1 = *(const uint32_t*)&sBh[nb][kb + tg * 2 + 8];
                uint32_t bl0 = *(const uint32_t*)&sBl[nb][kb + tg * 2];
                uint32_t bl1 = *(const uint32_t*)&sBl[nb][kb + tg * 2 + 8];
#pragma unroll
                for (int mi = 0; mi < 4; mi++) {
                    mma16816(acc[mi][ni], ah[mi][0], ah[mi][1], ah[mi][2], ah[mi][3], bh0, bh1);
                    mma16816(acc[mi][ni], ah[mi][0], ah[mi][1], ah[mi][2], ah[mi][3], bl0, bl1);
                    mma16816(acc[mi][ni], al[mi][0], al[mi][1], al[mi][2], al[mi][3], bh0, bh1);
                }
            }
        }
        __syncthreads();
    }

    // epilogue
#pragma unroll
    for (int mi = 0; mi < 4; mi++) {
#pragma unroll
        for (int ni = 0; ni < 4; ni++) {
            int r0 = m0 + wm * 64 + mi * 16 + g;
            int c0 = n0 + wn * 32 + ni * 8 + tg * 2;
#pragma unroll
            for (int h = 0; h < 2; h++) {
                int r = r0 + h * 8;
                float v0 = acc[mi][ni][h * 2 + 0];
                float v1 = acc[mi][ni][h * 2 + 1];
                if (mode == 0) { v0 += bias[c0]; v1 += bias[c0 + 1]; }
                else {
                    v0 = 1.0f / (1.0f + expf(-v0));
                    v1 = 1.0f / (1.0f + expf(-v1));
                }
                *(float2*)&C[(size_t)r * N + c0] = make_float2(v0, v1);
            }
        }
    }
}

// ---------------- recurrence step (mma, split-bf16) ----------------
#define SBK 128
#define SLDW (SBK + 8)   // 136

__global__ void __launch_bounds__(128) mma_step(const __nv_bfloat16* __restrict__ Whh,
                                                const __nv_bfloat16* __restrict__ Whl,
                                                const __nv_bfloat16* __restrict__ hh,
                                                const __nv_bfloat16* __restrict__ hl,
                                                const float* __restrict__ xwx_t,
                                                const float* __restrict__ gate_t,
                                                const float* __restrict__ z_t,
                                                float* __restrict__ hnext_f,
                                                __nv_bfloat16* __restrict__ hh_n,
                                                __nv_bfloat16* __restrict__ hl_n,
                                                float* __restrict__ out_t,
                                                const float* __restrict__ scale) {
    __shared__ __nv_bfloat16 sH[2][B_SZ][SLDW];   // hi, lo
    __shared__ __nv_bfloat16 sW[2][16][SLDW];
    int t = threadIdx.x;
    int warp = t >> 5, lane = t & 31;
    int g = lane >> 2, tg = lane & 3;
    int e0 = blockIdx.x * 16;

    float acc[2][4];
#pragma unroll
    for (int ni = 0; ni < 2; ni++)
#pragma unroll
        for (int j = 0; j < 4; j++) acc[ni][j] = 0.0f;

    for (int kt = 0; kt < D_SZ / SBK; kt++) {
        int k0 = kt * SBK;
        // H tiles: 64x128 bf16 = 1024 uint4 per array; 8 per thread
#pragma unroll
        for (int i = 0; i < 8; i++) {
            int lin = t + i * 128;
            int r = lin >> 4, c = (lin & 15) * 8;
            *(uint4*)&sH[0][r][c] = *(const uint4*)&hh[r * D_SZ + k0 + c];
            *(uint4*)&sH[1][r][c] = *(const uint4*)&hl[r * D_SZ + k0 + c];
        }
        // W tiles: 16x128 = 256 uint4 per array; 2 per thread
#pragma unroll
        for (int i = 0; i < 2; i++) {
            int lin = t + i * 128;
            int r = lin >> 4, c = (lin & 15) * 8;
            *(uint4*)&sW[0][r][c] = *(const uint4*)&Whh[(size_t)(e0 + r) * D_SZ + k0 + c];
            *(uint4*)&sW[1][r][c] = *(const uint4*)&Whl[(size_t)(e0 + r) * D_SZ + k0 + c];
        }
        __syncthreads();
#pragma unroll
        for (int ks = 0; ks < SBK / 16; ks++) {
            int kb = ks * 16;
            int rb = warp * 16;
            uint32_t ah0 = *(const uint32_t*)&sH[0][rb + g][kb + tg * 2];
            uint32_t ah1 = *(const uint32_t*)&sH[0][rb + g + 8][kb + tg * 2];
            uint32_t ah2 = *(const uint32_t*)&sH[0][rb + g][kb + tg * 2 + 8];
            uint32_t ah3 = *(const uint32_t*)&sH[0][rb + g + 8][kb + tg * 2 + 8];
            uint32_t al0 = *(const uint32_t*)&sH[1][rb + g][kb + tg * 2];
            uint32_t al1 = *(const uint32_t*)&sH[1][rb + g + 8][kb + tg * 2];
            uint32_t al2 = *(const uint32_t*)&sH[1][rb + g][kb + tg * 2 + 8];
            uint32_t al3 = *(const uint32_t*)&sH[1][rb + g + 8][kb + tg * 2 + 8];
#pragma unroll
            for (int ni = 0; ni < 2; ni++) {
                int nb = ni * 8 + g;
                uint32_t bh0 = *(const uint32_t*)&sW[0][nb][kb + tg * 2];
                uint32_t bh1 = *(const uint32_t*)&sW[0][nb][kb + tg * 2 + 8];
                uint32_t bl0 = *(const uint32_t*)&sW[1][nb][kb + tg * 2];
                uint32_t bl1 = *(const uint32_t*)&sW[1][nb][kb + tg * 2 + 8];
                mma16816(acc[ni], ah0, ah1, ah2, ah3, bh0, bh1);
                mma16816(acc[ni], ah0, ah1, ah2, ah3, bl0, bl1);
                mma16816(acc[ni], al0, al1, al2, al3, bh0, bh1);
            }
        }
        __syncthreads();
    }

    float s = scale[0];
#pragma unroll
    for (int ni = 0; ni < 2; ni++) {
#pragma unroll
        for (int h = 0; h < 2; h++) {
            int b = warp * 16 + g + h * 8;
            int e = e0 + ni * 8 + tg * 2;
            int idx = b * D_SZ + e;
#pragma unroll
            for (int j = 0; j < 2; j++) {
                float Rh = acc[ni][h * 2 + j] * s;
                float gg = gate_t[idx + j];
                float pre = xwx_t[idx + j] + Rh * gg;
                float hv = tanhf(pre);
                hnext_f[idx + j] = hv;
                __nv_bfloat16 hb = __float2bfloat16(hv);
                hh_n[idx + j] = hb;
                hl_n[idx + j] = __float2bfloat16(hv - __bfloat162float(hb));
                float zz = z_t[idx + j];
                out_t[idx + j] = hv * (zz / (1.0f + expf(-zz)));
            }
        }
    }
}

// ---------------- launch ----------------
extern "C" void kernel_launch(void* const* d_in, const int* in_sizes, int n_in,
                              void* d_out, int out_size) {
    const float* x    = (const float*)d_in[0];
    const float* z    = (const float*)d_in[1];
    const float* h0   = (const float*)d_in[2];
    const float* Wx   = (const float*)d_in[3];
    const float* Wh   = (const float*)d_in[4];
    const float* Wg   = (const float*)d_in[5];
    const float* bias = (const float*)d_in[6];
    float* out = (float*)d_out;

    float *p_u, *p_v, *p_w, *p_scale, *p_xwx, *p_gate, *p_hbuf;
    cudaGetSymbolAddress((void**)&p_u, g_u);
    cudaGetSymbolAddress((void**)&p_v, g_v);
    cudaGetSymbolAddress((void**)&p_w, g_w);
    cudaGetSymbolAddress((void**)&p_scale, g_scale);
    cudaGetSymbolAddress((void**)&p_xwx, g_xwx);
    cudaGetSymbolAddress((void**)&p_gate, g_gate);
    cudaGetSymbolAddress((void**)&p_hbuf, g_hbuf);

    __nv_bfloat16 *p_xhi, *p_xlo, *p_wxhi, *p_wxlo, *p_wghi, *p_wglo, *p_whhi, *p_whlo;
    __nv_bfloat16 *p_hhi, *p_hlo;
    cudaGetSymbolAddress((void**)&p_xhi, gx_hi);
    cudaGetSymbolAddress((void**)&p_xlo, gx_lo);
    cudaGetSymbolAddress((void**)&p_wxhi, gwx_hi);
    cudaGetSymbolAddress((void**)&p_wxlo, gwx_lo);
    cudaGetSymbolAddress((void**)&p_wghi, gwg_hi);
    cudaGetSymbolAddress((void**)&p_wglo, gwg_lo);
    cudaGetSymbolAddress((void**)&p_whhi, gwh_hi);
    cudaGetSymbolAddress((void**)&p_whlo, gwh_lo);
    cudaGetSymbolAddress((void**)&p_hhi, gh_hi);
    cudaGetSymbolAddress((void**)&p_hlo, gh_lo);

    long long need = (long long)TBD + (long long)(T_STEPS + 1) * BD;
    float* out_h = ((long long)out_size >= need) ? (out + TBD) : p_hbuf;

    // --- split conversions ---
    k_split<<<TBD / 4 / 256, 256>>>(x, p_xhi, p_xlo);
    k_split<<<DD / 4 / 256, 256>>>(Wx, p_wxhi, p_wxlo);
    k_split<<<DD / 4 / 256, 256>>>(Wg, p_wghi, p_wglo);
    k_split<<<DD / 4 / 256, 256>>>(Wh, p_whhi, p_whlo);
    k_split<<<BD / 4 / 256, 256>>>(h0, p_hhi, p_hlo);   // ping buffer 0

    // --- spectral norm of W_h (fp32, unchanged) ---
    k_init_u<<<1, 1024>>>(p_u);
    for (int it = 0; it < 3; it++) {
        k_mvT<<<16, 256>>>(Wh, p_u, p_v);
        k_norm<<<1, 1024>>>(p_v);
        k_mv<<<256, 256>>>(Wh, p_v, p_u);
        k_norm<<<1, 1024>>>(p_u);
    }
    k_mv<<<256, 256>>>(Wh, p_v, p_w);
    k_sigma<<<1, 1024>>>(p_u, p_w, p_scale);

    // --- input projections (split-bf16 tensor-core GEMMs) ---
    dim3 gg(D_SZ / GBN, (T_STEPS * B_SZ) / GBM);  // (16, 128)
    mma_gemm<<<gg, 256>>>(p_xhi, p_xlo, p_wxhi, p_wxlo, bias, p_xwx, 0);
    mma_gemm<<<gg, 256>>>(p_xhi, p_xlo, p_wghi, p_wglo, bias, p_gate, 1);

    // h[0] = h0
    cudaMemcpyAsync(out_h, h0, (size_t)BD * sizeof(float), cudaMemcpyDeviceToDevice);

    // --- sequential recurrence ---
    for (int t = 0; t < T_STEPS; t++) {
        int cur = t & 1, nxt = cur ^ 1;
        mma_step<<<D_SZ / 16, 128>>>(p_whhi, p_whlo,
                                     p_hhi + (size_t)cur * BD, p_hlo + (size_t)cur * BD,
                                     p_xwx + (size_t)t * BD,
                                     p_gate + (size_t)t * BD,
                                     z + (size_t)t * BD,
                                     out_h + (size_t)(t + 1) * BD,
                                     p_hhi + (size_t)nxt * BD, p_hlo + (size_t)nxt * BD,
                                     out + (size_t)t * BD,
                                     p_scale);
    }
}

// round 8
// speedup vs baseline: 3.3924x; 1.9647x over previous
#include <cuda_runtime.h>
#include <cuda_bf16.h>
#include <math.h>
#include <stdint.h>

#define T_STEPS 256
#define B_SZ 64
#define D_SZ 2048
#define BD (B_SZ * D_SZ)                 // 131072
#define TBD (T_STEPS * BD)               // 33554432
#define DD (D_SZ * D_SZ)                 // 4194304

// ---------------- device scratch (no allocations allowed) ----------------
__device__ float g_xwx[TBD];
__device__ float g_gate[TBD];
__device__ float g_hbuf[(T_STEPS + 1) * BD];
__device__ float g_u[D_SZ];
__device__ float g_v[D_SZ];
__device__ float g_w[D_SZ];
__device__ float g_scale;

__device__ __nv_bfloat16 gx_hi[TBD], gx_lo[TBD];
__device__ __nv_bfloat16 gwx_hi[DD], gwx_lo[DD];
__device__ __nv_bfloat16 gwg_hi[DD], gwg_lo[DD];
__device__ __nv_bfloat16 gwh_hi[DD], gwh_lo[DD];
__device__ __nv_bfloat16 gh_hi[2][BD], gh_lo[2][BD];

// ---------------- threefry2x32 (JAX partitionable mode) ----------------
__device__ __forceinline__ uint32_t rotl32(uint32_t x, int n) {
    return (x << n) | (x >> (32 - n));
}
#define TF_ROUND(x0, x1, r) do { x0 += x1; x1 = rotl32(x1, r); x1 ^= x0; } while (0)
#define TF_G_A(x0, x1) do { TF_ROUND(x0,x1,13); TF_ROUND(x0,x1,15); TF_ROUND(x0,x1,26); TF_ROUND(x0,x1,6); } while (0)
#define TF_G_B(x0, x1) do { TF_ROUND(x0,x1,17); TF_ROUND(x0,x1,29); TF_ROUND(x0,x1,16); TF_ROUND(x0,x1,24); } while (0)

__device__ __forceinline__ uint32_t threefry_part_bits(uint32_t cnt_hi, uint32_t cnt_lo) {
    const uint32_t ks0 = 0u, ks1 = 42u;
    const uint32_t ks2 = 0x1BD11BDAu ^ ks0 ^ ks1;
    uint32_t x0 = cnt_hi + ks0;
    uint32_t x1 = cnt_lo + ks1;
    TF_G_A(x0, x1); x0 += ks1; x1 += ks2 + 1u;
    TF_G_B(x0, x1); x0 += ks2; x1 += ks0 + 2u;
    TF_G_A(x0, x1); x0 += ks0; x1 += ks1 + 3u;
    TF_G_B(x0, x1); x0 += ks1; x1 += ks2 + 4u;
    TF_G_A(x0, x1); x0 += ks2; x1 += ks0 + 5u;
    return x0 ^ x1;
}

__device__ __forceinline__ float bits_to_normal(uint32_t bits) {
    float f = __uint_as_float((bits >> 9) | 0x3f800000u) - 1.0f;
    const float lo = -0.99999994f;
    const float span = 2.0f;
    float u = fmaf(f, span, lo);
    u = fmaxf(lo, u);
    return 1.41421356237f * erfinvf(u);
}

__global__ void k_init_u(float* __restrict__ u_out) {
    __shared__ float red[1024];
    __shared__ float inv;
    int i = threadIdx.x;
    float n0 = bits_to_normal(threefry_part_bits(0u, (uint32_t)i));
    float n1 = bits_to_normal(threefry_part_bits(0u, (uint32_t)(i + 1024)));
    red[i] = n0 * n0 + n1 * n1;
    __syncthreads();
    for (int s = 512; s > 0; s >>= 1) {
        if (i < s) red[i] += red[i + s];
        __syncthreads();
    }
    if (i == 0) inv = 1.0f / sqrtf(red[0]);
    __syncthreads();
    u_out[i] = n0 * inv;
    u_out[i + 1024] = n1 * inv;
}

__global__ void __launch_bounds__(256) k_mvT(const float* __restrict__ W,
                                             const float* __restrict__ u,
                                             float* __restrict__ v) {
    __shared__ float part[2][128];
    int t = threadIdx.x;
    int jl = t & 127, half = t >> 7;
    int j = blockIdx.x * 128 + jl;
    int i0 = half * 1024;
    float s = 0.0f;
#pragma unroll 8
    for (int i = 0; i < 1024; i++)
        s = fmaf(W[(size_t)(i0 + i) * D_SZ + j], u[i0 + i], s);
    part[half][jl] = s;
    __syncthreads();
    if (t < 128) v[blockIdx.x * 128 + t] = part[0][t] + part[1][t];
}

__global__ void __launch_bounds__(256) k_mv(const float* __restrict__ W,
                                            const float* __restrict__ v,
                                            float* __restrict__ o) {
    int gw = (blockIdx.x * blockDim.x + threadIdx.x) >> 5;
    int lane = threadIdx.x & 31;
    const float* row = W + (size_t)gw * D_SZ;
    float s = 0.0f;
#pragma unroll 8
    for (int k = lane; k < D_SZ; k += 32) s = fmaf(row[k], v[k], s);
#pragma unroll
    for (int off = 16; off > 0; off >>= 1)
        s += __shfl_xor_sync(0xffffffffu, s, off);
    if (lane == 0) o[gw] = s;
}

__global__ void k_norm(float* __restrict__ v) {
    __shared__ float red[1024];
    __shared__ float inv;
    int i = threadIdx.x;
    float a = v[i], b = v[i + 1024];
    red[i] = a * a + b * b;
    __syncthreads();
    for (int s = 512; s > 0; s >>= 1) {
        if (i < s) red[i] += red[i + s];
        __syncthreads();
    }
    if (i == 0) inv = 1.0f / (sqrtf(red[0]) + 1e-8f);
    __syncthreads();
    v[i] = a * inv;
    v[i + 1024] = b * inv;
}

__global__ void k_sigma(const float* __restrict__ u, const float* __restrict__ w,
                        float* __restrict__ scale) {
    __shared__ float red[1024];
    int i = threadIdx.x;
    red[i] = u[i] * w[i] + u[i + 1024] * w[i + 1024];
    __syncthreads();
    for (int s = 512; s > 0; s >>= 1) {
        if (i < s) red[i] += red[i + s];
        __syncthreads();
    }
    if (i == 0) scale[0] = 0.99f / (fabsf(red[0]) + 1e-8f);
}

// ---------------- fp32 -> (hi, lo) bf16 split ----------------
__global__ void __launch_bounds__(256) k_split(const float* __restrict__ src,
                                               __nv_bfloat16* __restrict__ hi,
                                               __nv_bfloat16* __restrict__ lo) {
    int i = blockIdx.x * blockDim.x + threadIdx.x;
    float4 v = ((const float4*)src)[i];
    union { __nv_bfloat16 b[4]; uint2 u; } ph, pl;
    float vv[4] = {v.x, v.y, v.z, v.w};
#pragma unroll
    for (int j = 0; j < 4; j++) {
        __nv_bfloat16 h = __float2bfloat16(vv[j]);
        ph.b[j] = h;
        pl.b[j] = __float2bfloat16(vv[j] - __bfloat162float(h));
    }
    ((uint2*)hi)[i] = ph.u;
    ((uint2*)lo)[i] = pl.u;
}

// ---------------- async copy + ldmatrix helpers ----------------
__device__ __forceinline__ uint32_t smem_u32(const void* p) {
    uint32_t a;
    asm("{ .reg .u64 t; cvta.to.shared.u64 t, %1; cvt.u32.u64 %0, t; }" : "=r"(a) : "l"(p));
    return a;
}
__device__ __forceinline__ void cp16(uint32_t dst, const void* src) {
    asm volatile("cp.async.cg.shared.global [%0], [%1], 16;" :: "r"(dst), "l"(src));
}
__device__ __forceinline__ void cp_commit() {
    asm volatile("cp.async.commit_group;" ::: "memory");
}
template <int N> __device__ __forceinline__ void cp_wait() {
    asm volatile("cp.async.wait_group %0;" :: "n"(N) : "memory");
}
__device__ __forceinline__ void ldsm_x4(uint32_t& r0, uint32_t& r1, uint32_t& r2, uint32_t& r3,
                                        uint32_t addr) {
    asm volatile("ldmatrix.sync.aligned.m8n8.x4.shared.b16 {%0,%1,%2,%3}, [%4];"
                 : "=r"(r0), "=r"(r1), "=r"(r2), "=r"(r3) : "r"(addr));
}
__device__ __forceinline__ void mma16816(float* c,
                                         uint32_t a0, uint32_t a1, uint32_t a2, uint32_t a3,
                                         uint32_t b0, uint32_t b1) {
    asm volatile(
        "mma.sync.aligned.m16n8k16.row.col.f32.bf16.bf16.f32 "
        "{%0,%1,%2,%3}, {%4,%5,%6,%7}, {%8,%9}, {%0,%1,%2,%3};\n"
        : "+f"(c[0]), "+f"(c[1]), "+f"(c[2]), "+f"(c[3])
        : "r"(a0), "r"(a1), "r"(a2), "r"(a3), "r"(b0), "r"(b1));
}

// ---------------- pipelined HMMA GEMM: C[m,n] = sum_k A[m,k]*B[n,k], 3-term split ------
// 256 thr, 8 warps (2x4), tile 128x128xBK32, 2-stage cp.async, ldmatrix fragments.
// SMEM stage: Ah(8K) Al(8K) Bh(8K) Bl(8K) = 32K; 2 stages = 64K dynamic.
// 64B rows (32 bf16), swizzle: chunk g (0..3) -> g ^ ((r>>1)&3).
#define GEMM_SMEM 65536

__global__ void __launch_bounds__(256, 1) mma_gemm2(const __nv_bfloat16* __restrict__ Ah,
                                                    const __nv_bfloat16* __restrict__ Al,
                                                    const __nv_bfloat16* __restrict__ Bh,
                                                    const __nv_bfloat16* __restrict__ Bl,
                                                    const float* __restrict__ bias,
                                                    float* __restrict__ C,
                                                    int mode) {
    extern __shared__ char smem[];
    uint32_t sb = smem_u32(smem);
    const int K = D_SZ, N = D_SZ;
    int t = threadIdx.x;
    int wid = t >> 5, lane = t & 31;
    int wm = wid >> 2, wn = wid & 3;     // warp tile 64x32
    int m0 = blockIdx.y * 128, n0 = blockIdx.x * 128;

    float acc[4][4][4];
#pragma unroll
    for (int mi = 0; mi < 4; mi++)
#pragma unroll
        for (int ni = 0; ni < 4; ni++)
#pragma unroll
            for (int j = 0; j < 4; j++) acc[mi][ni][j] = 0.0f;

    // loader lambda (manual): stage s, k-chunk kt
    const int r0l = t >> 2, g0l = t & 3;               // chunk 0: c = t
    const int r1l = (t + 256) >> 2, g1l = t & 3;       // chunk 1: c = t+256
    uint32_t off0 = (uint32_t)(r0l * 64 + ((g0l ^ ((r0l >> 1) & 3)) << 4));
    uint32_t off1 = (uint32_t)(r1l * 64 + ((g1l ^ ((r1l >> 1) & 3)) << 4));

#define G_LOAD(s, kt)  do {                                                              \
        int k0 = (kt) * 32;                                                              \
        uint32_t st = sb + (s) * 32768;                                                  \
        cp16(st + off0,         &Ah[(size_t)(m0 + r0l) * K + k0 + g0l * 8]);             \
        cp16(st + 8192 + off0,  &Al[(size_t)(m0 + r0l) * K + k0 + g0l * 8]);             \
        cp16(st + 16384 + off0, &Bh[(size_t)(n0 + r0l) * K + k0 + g0l * 8]);             \
        cp16(st + 24576 + off0, &Bl[(size_t)(n0 + r0l) * K + k0 + g0l * 8]);             \
        cp16(st + off1,         &Ah[(size_t)(m0 + r1l) * K + k0 + g1l * 8]);             \
        cp16(st + 8192 + off1,  &Al[(size_t)(m0 + r1l) * K + k0 + g1l * 8]);             \
        cp16(st + 16384 + off1, &Bh[(size_t)(n0 + r1l) * K + k0 + g1l * 8]);             \
        cp16(st + 24576 + off1, &Bl[(size_t)(n0 + r1l) * K + k0 + g1l * 8]);             \
        cp_commit();                                                                     \
    } while (0)

    G_LOAD(0, 0);

    const int NKT = K / 32;  // 64
    for (int kt = 0; kt < NKT; kt++) {
        int s = kt & 1;
        if (kt < NKT - 1) {
            G_LOAD(s ^ 1, kt + 1);
            cp_wait<1>();
        } else {
            cp_wait<0>();
        }
        __syncthreads();
        uint32_t st = sb + s * 32768;
#pragma unroll
        for (int ks = 0; ks < 2; ks++) {
            int kb = ks * 16;
            // B fragments: 2 x ldmatrix.x4 per (hi/lo), covering 4 n-blocks of 8
            uint32_t bh[4][2], bl[4][2];
            {
                int nrow = wn * 32 + ((lane >> 4) << 3) + (lane & 7);
                int gg = (kb >> 3) + ((lane >> 3) & 1);
                uint32_t a0 = (uint32_t)(nrow * 64 + ((gg ^ ((nrow >> 1) & 3)) << 4));
                int nrow2 = nrow + 16;
                uint32_t a1 = (uint32_t)(nrow2 * 64 + ((gg ^ ((nrow2 >> 1) & 3)) << 4));
                ldsm_x4(bh[0][0], bh[0][1], bh[1][0], bh[1][1], st + 16384 + a0);
                ldsm_x4(bh[2][0], bh[2][1], bh[3][0], bh[3][1], st + 16384 + a1);
                ldsm_x4(bl[0][0], bl[0][1], bl[1][0], bl[1][1], st + 24576 + a0);
                ldsm_x4(bl[2][0], bl[2][1], bl[3][0], bl[3][1], st + 24576 + a1);
            }
#pragma unroll
            for (int mi = 0; mi < 4; mi++) {
                int row = wm * 64 + mi * 16 + (lane & 15);
                int gg = (kb >> 3) + (lane >> 4);
                uint32_t aad = (uint32_t)(row * 64 + ((gg ^ ((row >> 1) & 3)) << 4));
                uint32_t ah0, ah1, ah2, ah3, al0, al1, al2, al3;
                ldsm_x4(ah0, ah1, ah2, ah3, st + aad);
                ldsm_x4(al0, al1, al2, al3, st + 8192 + aad);
#pragma unroll
                for (int ni = 0; ni < 4; ni++) {
                    mma16816(acc[mi][ni], ah0, ah1, ah2, ah3, bh[ni][0], bh[ni][1]);
                    mma16816(acc[mi][ni], ah0, ah1, ah2, ah3, bl[ni][0], bl[ni][1]);
                    mma16816(acc[mi][ni], al0, al1, al2, al3, bh[ni][0], bh[ni][1]);
                }
            }
        }
        __syncthreads();
    }
#undef G_LOAD

    int g = lane >> 2, tg = lane & 3;
#pragma unroll
    for (int mi = 0; mi < 4; mi++) {
#pragma unroll
        for (int ni = 0; ni < 4; ni++) {
            int r0 = m0 + wm * 64 + mi * 16 + g;
            int c0 = n0 + wn * 32 + ni * 8 + tg * 2;
#pragma unroll
            for (int h = 0; h < 2; h++) {
                int r = r0 + h * 8;
                float v0 = acc[mi][ni][h * 2 + 0];
                float v1 = acc[mi][ni][h * 2 + 1];
                if (mode == 0) { v0 += bias[c0]; v1 += bias[c0 + 1]; }
                else {
                    v0 = 1.0f / (1.0f + expf(-v0));
                    v1 = 1.0f / (1.0f + expf(-v1));
                }
                *(float2*)&C[(size_t)r * N + c0] = make_float2(v0, v1);
            }
        }
    }
}

// ---------------- pipelined recurrence step ----------------
// 256 thr, 8 warps (wm=wid&3 -> m16 of 64 batch; wn=wid>>2 -> n16 of 32 feats).
// grid 64 CTAs x 32 feats. BK=64, 2-stage cp.async.
// SMEM stage: Hh(8K) Hl(8K) Wh(4K) Wl(4K) = 24K; x2 = 48K dynamic.
// 128B rows (64 bf16), swizzle: chunk g (0..7) -> g ^ (r&7).
#define STEP_SMEM 49152

__global__ void __launch_bounds__(256, 1) mma_step2(const __nv_bfloat16* __restrict__ Whh,
                                                    const __nv_bfloat16* __restrict__ Whl,
                                                    const __nv_bfloat16* __restrict__ hh,
                                                    const __nv_bfloat16* __restrict__ hl,
                                                    const float* __restrict__ xwx_t,
                                                    const float* __restrict__ gate_t,
                                                    const float* __restrict__ z_t,
                                                    float* __restrict__ hnext_f,
                                                    __nv_bfloat16* __restrict__ hh_n,
                                                    __nv_bfloat16* __restrict__ hl_n,
                                                    float* __restrict__ out_t,
                                                    const float* __restrict__ scale) {
    extern __shared__ char smem[];
    uint32_t sb = smem_u32(smem);
    int t = threadIdx.x;
    int wid = t >> 5, lane = t & 31;
    int wm = wid & 3, wn = wid >> 2;
    int e0 = blockIdx.x * 32;

    float acc[2][4];
#pragma unroll
    for (int ni = 0; ni < 2; ni++)
#pragma unroll
        for (int j = 0; j < 4; j++) acc[ni][j] = 0.0f;

    const int rh0 = t >> 3, gh0 = t & 7;             // H chunk 0 (c = t)
    const int rh1 = (t + 256) >> 3;                  // H chunk 1 (c = t+256), g same
    uint32_t hoff0 = (uint32_t)(rh0 * 128 + ((gh0 ^ (rh0 & 7)) << 4));
    uint32_t hoff1 = (uint32_t)(rh1 * 128 + ((gh0 ^ (rh1 & 7)) << 4));
    const int rw0 = t >> 3, gw0 = t & 7;             // W chunk (32 rows x 8 = 256)
    uint32_t woff0 = (uint32_t)(rw0 * 128 + ((gw0 ^ (rw0 & 7)) << 4));

#define S_LOAD(s, kt)  do {                                                               \
        int k0 = (kt) * 64;                                                               \
        uint32_t st = sb + (s) * 24576;                                                   \
        cp16(st + hoff0,         &hh[rh0 * D_SZ + k0 + gh0 * 8]);                         \
        cp16(st + hoff1,         &hh[rh1 * D_SZ + k0 + gh0 * 8]);                         \
        cp16(st + 8192 + hoff0,  &hl[rh0 * D_SZ + k0 + gh0 * 8]);                         \
        cp16(st + 8192 + hoff1,  &hl[rh1 * D_SZ + k0 + gh0 * 8]);                         \
        cp16(st + 16384 + woff0, &Whh[(size_t)(e0 + rw0) * D_SZ + k0 + gw0 * 8]);         \
        cp16(st + 20480 + woff0, &Whl[(size_t)(e0 + rw0) * D_SZ + k0 + gw0 * 8]);         \
        cp_commit();                                                                      \
    } while (0)

    S_LOAD(0, 0);

    const int NKT = D_SZ / 64;  // 32
    for (int kt = 0; kt < NKT; kt++) {
        int s = kt & 1;
        if (kt < NKT - 1) {
            S_LOAD(s ^ 1, kt + 1);
            cp_wait<1>();
        } else {
            cp_wait<0>();
        }
        __syncthreads();
        uint32_t st = sb + s * 24576;
#pragma unroll
        for (int ks = 0; ks < 4; ks++) {
            int kb = ks * 16;
            uint32_t ah0, ah1, ah2, ah3, al0, al1, al2, al3;
            {
                int row = wm * 16 + (lane & 15);
                int gg = (kb >> 3) + (lane >> 4);
                uint32_t aad = (uint32_t)(row * 128 + ((gg ^ (row & 7)) << 4));
                ldsm_x4(ah0, ah1, ah2, ah3, st + aad);
                ldsm_x4(al0, al1, al2, al3, st + 8192 + aad);
            }
            uint32_t bh[2][2], bl[2][2];
            {
                int nrow = wn * 16 + ((lane >> 4) << 3) + (lane & 7);
                int gg = (kb >> 3) + ((lane >> 3) & 1);
                uint32_t bad = (uint32_t)(nrow * 128 + ((gg ^ (nrow & 7)) << 4));
                ldsm_x4(bh[0][0], bh[0][1], bh[1][0], bh[1][1], st + 16384 + bad);
                ldsm_x4(bl[0][0], bl[0][1], bl[1][0], bl[1][1], st + 20480 + bad);
            }
#pragma unroll
            for (int ni = 0; ni < 2; ni++) {
                mma16816(acc[ni], ah0, ah1, ah2, ah3, bh[ni][0], bh[ni][1]);
                mma16816(acc[ni], ah0, ah1, ah2, ah3, bl[ni][0], bl[ni][1]);
                mma16816(acc[ni], al0, al1, al2, al3, bh[ni][0], bh[ni][1]);
            }
        }
        __syncthreads();
    }
#undef S_LOAD

    float s = scale[0];
    int g = lane >> 2, tg = lane & 3;
#pragma unroll
    for (int ni = 0; ni < 2; ni++) {
#pragma unroll
        for (int h = 0; h < 2; h++) {
            int b = wm * 16 + g + h * 8;
            int e = e0 + wn * 16 + ni * 8 + tg * 2;
            int idx = b * D_SZ + e;
#pragma unroll
            for (int j = 0; j < 2; j++) {
                float Rh = acc[ni][h * 2 + j] * s;
                float gg = gate_t[idx + j];
                float pre = xwx_t[idx + j] + Rh * gg;
                float hv = tanhf(pre);
                hnext_f[idx + j] = hv;
                __nv_bfloat16 hb = __float2bfloat16(hv);
                hh_n[idx + j] = hb;
                hl_n[idx + j] = __float2bfloat16(hv - __bfloat162float(hb));
                float zz = z_t[idx + j];
                out_t[idx + j] = hv * (zz / (1.0f + expf(-zz)));
            }
        }
    }
}

// ---------------- launch ----------------
extern "C" void kernel_launch(void* const* d_in, const int* in_sizes, int n_in,
                              void* d_out, int out_size) {
    const float* x    = (const float*)d_in[0];
    const float* z    = (const float*)d_in[1];
    const float* h0   = (const float*)d_in[2];
    const float* Wx   = (const float*)d_in[3];
    const float* Wh   = (const float*)d_in[4];
    const float* Wg   = (const float*)d_in[5];
    const float* bias = (const float*)d_in[6];
    float* out = (float*)d_out;

    float *p_u, *p_v, *p_w, *p_scale, *p_xwx, *p_gate, *p_hbuf;
    cudaGetSymbolAddress((void**)&p_u, g_u);
    cudaGetSymbolAddress((void**)&p_v, g_v);
    cudaGetSymbolAddress((void**)&p_w, g_w);
    cudaGetSymbolAddress((void**)&p_scale, g_scale);
    cudaGetSymbolAddress((void**)&p_xwx, g_xwx);
    cudaGetSymbolAddress((void**)&p_gate, g_gate);
    cudaGetSymbolAddress((void**)&p_hbuf, g_hbuf);

    __nv_bfloat16 *p_xhi, *p_xlo, *p_wxhi, *p_wxlo, *p_wghi, *p_wglo, *p_whhi, *p_whlo;
    __nv_bfloat16 *p_hhi, *p_hlo;
    cudaGetSymbolAddress((void**)&p_xhi, gx_hi);
    cudaGetSymbolAddress((void**)&p_xlo, gx_lo);
    cudaGetSymbolAddress((void**)&p_wxhi, gwx_hi);
    cudaGetSymbolAddress((void**)&p_wxlo, gwx_lo);
    cudaGetSymbolAddress((void**)&p_wghi, gwg_hi);
    cudaGetSymbolAddress((void**)&p_wglo, gwg_lo);
    cudaGetSymbolAddress((void**)&p_whhi, gwh_hi);
    cudaGetSymbolAddress((void**)&p_whlo, gwh_lo);
    cudaGetSymbolAddress((void**)&p_hhi, gh_hi);
    cudaGetSymbolAddress((void**)&p_hlo, gh_lo);

    cudaFuncSetAttribute(mma_gemm2, cudaFuncAttributeMaxDynamicSharedMemorySize, GEMM_SMEM);
    cudaFuncSetAttribute(mma_step2, cudaFuncAttributeMaxDynamicSharedMemorySize, STEP_SMEM);

    long long need = (long long)TBD + (long long)(T_STEPS + 1) * BD;
    float* out_h = ((long long)out_size >= need) ? (out + TBD) : p_hbuf;

    // --- split conversions ---
    k_split<<<TBD / 4 / 256, 256>>>(x, p_xhi, p_xlo);
    k_split<<<DD / 4 / 256, 256>>>(Wx, p_wxhi, p_wxlo);
    k_split<<<DD / 4 / 256, 256>>>(Wg, p_wghi, p_wglo);
    k_split<<<DD / 4 / 256, 256>>>(Wh, p_whhi, p_whlo);
    k_split<<<BD / 4 / 256, 256>>>(h0, p_hhi, p_hlo);

    // --- spectral norm of W_h (fp32) ---
    k_init_u<<<1, 1024>>>(p_u);
    for (int it = 0; it < 3; it++) {
        k_mvT<<<16, 256>>>(Wh, p_u, p_v);
        k_norm<<<1, 1024>>>(p_v);
        k_mv<<<256, 256>>>(Wh, p_v, p_u);
        k_norm<<<1, 1024>>>(p_u);
    }
    k_mv<<<256, 256>>>(Wh, p_v, p_w);
    k_sigma<<<1, 1024>>>(p_u, p_w, p_scale);

    // --- input projections ---
    dim3 gg(D_SZ / 128, (T_STEPS * B_SZ) / 128);  // (16, 128)
    mma_gemm2<<<gg, 256, GEMM_SMEM>>>(p_xhi, p_xlo, p_wxhi, p_wxlo, bias, p_xwx, 0);
    mma_gemm2<<<gg, 256, GEMM_SMEM>>>(p_xhi, p_xlo, p_wghi, p_wglo, bias, p_gate, 1);

    // h[0] = h0
    cudaMemcpyAsync(out_h, h0, (size_t)BD * sizeof(float), cudaMemcpyDeviceToDevice);

    // --- sequential recurrence ---
    for (int t = 0; t < T_STEPS; t++) {
        int cur = t & 1, nxt = cur ^ 1;
        mma_step2<<<64, 256, STEP_SMEM>>>(p_whhi, p_whlo,
                                          p_hhi + (size_t)cur * BD, p_hlo + (size_t)cur * BD,
                                          p_xwx + (size_t)t * BD,
                                          p_gate + (size_t)t * BD,
                                          z + (size_t)t * BD,
                                          out_h + (size_t)(t + 1) * BD,
                                          p_hhi + (size_t)nxt * BD, p_hlo + (size_t)nxt * BD,
                                          out + (size_t)t * BD,
                                          p_scale);
    }
}

// round 9
// speedup vs baseline: 3.5182x; 1.0371x over previous
#include <cuda_runtime.h>
#include <cuda_bf16.h>
#include <math.h>
#include <stdint.h>

#define T_STEPS 256
#define B_SZ 64
#define D_SZ 2048
#define BD (B_SZ * D_SZ)                 // 131072
#define TBD (T_STEPS * BD)               // 33554432
#define DD (D_SZ * D_SZ)                 // 4194304

// ---------------- device scratch (no allocations allowed) ----------------
__device__ float g_xwx[TBD];
__device__ float g_gate[TBD];
__device__ float g_hbuf[(T_STEPS + 1) * BD];
__device__ float g_u[D_SZ];
__device__ float g_v[D_SZ];
__device__ float g_w[D_SZ];
__device__ float g_scale;

__device__ __nv_bfloat16 gx_hi[TBD], gx_lo[TBD];
__device__ __nv_bfloat16 gwx_hi[DD], gwx_lo[DD];
__device__ __nv_bfloat16 gwg_hi[DD], gwg_lo[DD];
__device__ __nv_bfloat16 gwh_hi[DD], gwh_lo[DD];
__device__ __nv_bfloat16 gh_hi[2][BD], gh_lo[2][BD];

// ---------------- threefry2x32 (JAX partitionable mode) ----------------
__device__ __forceinline__ uint32_t rotl32(uint32_t x, int n) {
    return (x << n) | (x >> (32 - n));
}
#define TF_ROUND(x0, x1, r) do { x0 += x1; x1 = rotl32(x1, r); x1 ^= x0; } while (0)
#define TF_G_A(x0, x1) do { TF_ROUND(x0,x1,13); TF_ROUND(x0,x1,15); TF_ROUND(x0,x1,26); TF_ROUND(x0,x1,6); } while (0)
#define TF_G_B(x0, x1) do { TF_ROUND(x0,x1,17); TF_ROUND(x0,x1,29); TF_ROUND(x0,x1,16); TF_ROUND(x0,x1,24); } while (0)

__device__ __forceinline__ uint32_t threefry_part_bits(uint32_t cnt_hi, uint32_t cnt_lo) {
    const uint32_t ks0 = 0u, ks1 = 42u;
    const uint32_t ks2 = 0x1BD11BDAu ^ ks0 ^ ks1;
    uint32_t x0 = cnt_hi + ks0;
    uint32_t x1 = cnt_lo + ks1;
    TF_G_A(x0, x1); x0 += ks1; x1 += ks2 + 1u;
    TF_G_B(x0, x1); x0 += ks2; x1 += ks0 + 2u;
    TF_G_A(x0, x1); x0 += ks0; x1 += ks1 + 3u;
    TF_G_B(x0, x1); x0 += ks1; x1 += ks2 + 4u;
    TF_G_A(x0, x1); x0 += ks2; x1 += ks0 + 5u;
    return x0 ^ x1;
}

__device__ __forceinline__ float bits_to_normal(uint32_t bits) {
    float f = __uint_as_float((bits >> 9) | 0x3f800000u) - 1.0f;
    const float lo = -0.99999994f;
    const float span = 2.0f;
    float u = fmaf(f, span, lo);
    u = fmaxf(lo, u);
    return 1.41421356237f * erfinvf(u);
}

__global__ void k_init_u(float* __restrict__ u_out) {
    __shared__ float red[1024];
    __shared__ float inv;
    int i = threadIdx.x;
    float n0 = bits_to_normal(threefry_part_bits(0u, (uint32_t)i));
    float n1 = bits_to_normal(threefry_part_bits(0u, (uint32_t)(i + 1024)));
    red[i] = n0 * n0 + n1 * n1;
    __syncthreads();
    for (int s = 512; s > 0; s >>= 1) {
        if (i < s) red[i] += red[i + s];
        __syncthreads();
    }
    if (i == 0) inv = 1.0f / sqrtf(red[0]);
    __syncthreads();
    u_out[i] = n0 * inv;
    u_out[i + 1024] = n1 * inv;
}

__global__ void __launch_bounds__(256) k_mvT(const float* __restrict__ W,
                                             const float* __restrict__ u,
                                             float* __restrict__ v) {
    __shared__ float part[2][128];
    int t = threadIdx.x;
    int jl = t & 127, half = t >> 7;
    int j = blockIdx.x * 128 + jl;
    int i0 = half * 1024;
    float s = 0.0f;
#pragma unroll 8
    for (int i = 0; i < 1024; i++)
        s = fmaf(W[(size_t)(i0 + i) * D_SZ + j], u[i0 + i], s);
    part[half][jl] = s;
    __syncthreads();
    if (t < 128) v[blockIdx.x * 128 + t] = part[0][t] + part[1][t];
}

__global__ void __launch_bounds__(256) k_mv(const float* __restrict__ W,
                                            const float* __restrict__ v,
                                            float* __restrict__ o) {
    int gw = (blockIdx.x * blockDim.x + threadIdx.x) >> 5;
    int lane = threadIdx.x & 31;
    const float* row = W + (size_t)gw * D_SZ;
    float s = 0.0f;
#pragma unroll 8
    for (int k = lane; k < D_SZ; k += 32) s = fmaf(row[k], v[k], s);
#pragma unroll
    for (int off = 16; off > 0; off >>= 1)
        s += __shfl_xor_sync(0xffffffffu, s, off);
    if (lane == 0) o[gw] = s;
}

__global__ void k_norm(float* __restrict__ v) {
    __shared__ float red[1024];
    __shared__ float inv;
    int i = threadIdx.x;
    float a = v[i], b = v[i + 1024];
    red[i] = a * a + b * b;
    __syncthreads();
    for (int s = 512; s > 0; s >>= 1) {
        if (i < s) red[i] += red[i + s];
        __syncthreads();
    }
    if (i == 0) inv = 1.0f / (sqrtf(red[0]) + 1e-8f);
    __syncthreads();
    v[i] = a * inv;
    v[i + 1024] = b * inv;
}

__global__ void k_sigma(const float* __restrict__ u, const float* __restrict__ w,
                        float* __restrict__ scale) {
    __shared__ float red[1024];
    int i = threadIdx.x;
    red[i] = u[i] * w[i] + u[i + 1024] * w[i + 1024];
    __syncthreads();
    for (int s = 512; s > 0; s >>= 1) {
        if (i < s) red[i] += red[i + s];
        __syncthreads();
    }
    if (i == 0) scale[0] = 0.99f / (fabsf(red[0]) + 1e-8f);
}

// ---------------- fp32 -> (hi, lo) bf16 split ----------------
__global__ void __launch_bounds__(256) k_split(const float* __restrict__ src,
                                               __nv_bfloat16* __restrict__ hi,
                                               __nv_bfloat16* __restrict__ lo) {
    int i = blockIdx.x * blockDim.x + threadIdx.x;
    float4 v = ((const float4*)src)[i];
    union { __nv_bfloat16 b[4]; uint2 u; } ph, pl;
    float vv[4] = {v.x, v.y, v.z, v.w};
#pragma unroll
    for (int j = 0; j < 4; j++) {
        __nv_bfloat16 h = __float2bfloat16(vv[j]);
        ph.b[j] = h;
        pl.b[j] = __float2bfloat16(vv[j] - __bfloat162float(h));
    }
    ((uint2*)hi)[i] = ph.u;
    ((uint2*)lo)[i] = pl.u;
}

// ---------------- async copy + ldmatrix helpers ----------------
__device__ __forceinline__ uint32_t smem_u32(const void* p) {
    uint32_t a;
    asm("{ .reg .u64 t; cvta.to.shared.u64 t, %1; cvt.u32.u64 %0, t; }" : "=r"(a) : "l"(p));
    return a;
}
__device__ __forceinline__ void cp16(uint32_t dst, const void* src) {
    asm volatile("cp.async.cg.shared.global [%0], [%1], 16;" :: "r"(dst), "l"(src));
}
__device__ __forceinline__ void cp_commit() {
    asm volatile("cp.async.commit_group;" ::: "memory");
}
template <int N> __device__ __forceinline__ void cp_wait() {
    asm volatile("cp.async.wait_group %0;" :: "n"(N) : "memory");
}
__device__ __forceinline__ void ldsm_x4(uint32_t& r0, uint32_t& r1, uint32_t& r2, uint32_t& r3,
                                        uint32_t addr) {
    asm volatile("ldmatrix.sync.aligned.m8n8.x4.shared.b16 {%0,%1,%2,%3}, [%4];"
                 : "=r"(r0), "=r"(r1), "=r"(r2), "=r"(r3) : "r"(addr));
}
__device__ __forceinline__ void mma16816(float* c,
                                         uint32_t a0, uint32_t a1, uint32_t a2, uint32_t a3,
                                         uint32_t b0, uint32_t b1) {
    asm volatile(
        "mma.sync.aligned.m16n8k16.row.col.f32.bf16.bf16.f32 "
        "{%0,%1,%2,%3}, {%4,%5,%6,%7}, {%8,%9}, {%0,%1,%2,%3};\n"
        : "+f"(c[0]), "+f"(c[1]), "+f"(c[2]), "+f"(c[3])
        : "r"(a0), "r"(a1), "r"(a2), "r"(a3), "r"(b0), "r"(b1));
}

// ---------------- pipelined HMMA GEMM, tile 128x64, 2 CTAs/SM ----------------
// 256 thr, 8 warps (4 wm x 2 wn), warp tile 32x32, BK=32, 2-stage cp.async.
// SMEM stage: Ah(8K) Al(8K) Bh(4K) Bl(4K) = 24K; 2 stages = 48K dynamic.
// 64B rows (32 bf16), swizzle: chunk g (0..3) -> g ^ ((r>>1)&3).
#define GEMM_SMEM 49152

__global__ void __launch_bounds__(256, 2) mma_gemm3(const __nv_bfloat16* __restrict__ Ah,
                                                    const __nv_bfloat16* __restrict__ Al,
                                                    const __nv_bfloat16* __restrict__ Bh,
                                                    const __nv_bfloat16* __restrict__ Bl,
                                                    const float* __restrict__ bias,
                                                    float* __restrict__ C,
                                                    int mode) {
    extern __shared__ char smem[];
    uint32_t sb = smem_u32(smem);
    const int K = D_SZ, N = D_SZ;
    int t = threadIdx.x;
    int wid = t >> 5, lane = t & 31;
    int wm = wid >> 1, wn = wid & 1;     // warp tile 32x32
    int m0 = blockIdx.y * 128, n0 = blockIdx.x * 64;

    float acc[2][4][4];
#pragma unroll
    for (int mi = 0; mi < 2; mi++)
#pragma unroll
        for (int ni = 0; ni < 4; ni++)
#pragma unroll
            for (int j = 0; j < 4; j++) acc[mi][ni][j] = 0.0f;

    // A: 512 cp16/array, 2 per thread; B: 256 cp16/array, 1 per thread
    const int ra0 = t >> 2, ga = t & 3;
    const int ra1 = (t + 256) >> 2;
    uint32_t aoff0 = (uint32_t)(ra0 * 64 + ((ga ^ ((ra0 >> 1) & 3)) << 4));
    uint32_t aoff1 = (uint32_t)(ra1 * 64 + ((ga ^ ((ra1 >> 1) & 3)) << 4));
    const int rb0 = t >> 2;              // 0..63
    uint32_t boff0 = (uint32_t)(rb0 * 64 + ((ga ^ ((rb0 >> 1) & 3)) << 4));

#define G_LOAD(s, kt)  do {                                                              \
        int k0 = (kt) * 32;                                                              \
        uint32_t st = sb + (s) * 24576;                                                  \
        cp16(st + aoff0,         &Ah[(size_t)(m0 + ra0) * K + k0 + ga * 8]);             \
        cp16(st + aoff1,         &Ah[(size_t)(m0 + ra1) * K + k0 + ga * 8]);             \
        cp16(st + 8192 + aoff0,  &Al[(size_t)(m0 + ra0) * K + k0 + ga * 8]);             \
        cp16(st + 8192 + aoff1,  &Al[(size_t)(m0 + ra1) * K + k0 + ga * 8]);             \
        cp16(st + 16384 + boff0, &Bh[(size_t)(n0 + rb0) * K + k0 + ga * 8]);             \
        cp16(st + 20480 + boff0, &Bl[(size_t)(n0 + rb0) * K + k0 + ga * 8]);             \
        cp_commit();                                                                     \
    } while (0)

    G_LOAD(0, 0);

    const int NKT = K / 32;  // 64
    for (int kt = 0; kt < NKT; kt++) {
        int s = kt & 1;
        if (kt < NKT - 1) {
            G_LOAD(s ^ 1, kt + 1);
            cp_wait<1>();
        } else {
            cp_wait<0>();
        }
        __syncthreads();
        uint32_t st = sb + s * 24576;
#pragma unroll
        for (int ks = 0; ks < 2; ks++) {
            int kb = ks * 16;
            // B fragments: 2 x ldmatrix.x4 per (hi/lo) -> 4 n-blocks of 8
            uint32_t bh[4][2], bl[4][2];
            {
                int nrow = wn * 32 + ((lane >> 4) << 3) + (lane & 7);
                int gg = (kb >> 3) + ((lane >> 3) & 1);
                uint32_t a0 = (uint32_t)(nrow * 64 + ((gg ^ ((nrow >> 1) & 3)) << 4));
                int nrow2 = nrow + 16;
                uint32_t a1 = (uint32_t)(nrow2 * 64 + ((gg ^ ((nrow2 >> 1) & 3)) << 4));
                ldsm_x4(bh[0][0], bh[0][1], bh[1][0], bh[1][1], st + 16384 + a0);
                ldsm_x4(bh[2][0], bh[2][1], bh[3][0], bh[3][1], st + 16384 + a1);
                ldsm_x4(bl[0][0], bl[0][1], bl[1][0], bl[1][1], st + 20480 + a0);
                ldsm_x4(bl[2][0], bl[2][1], bl[3][0], bl[3][1], st + 20480 + a1);
            }
#pragma unroll
            for (int mi = 0; mi < 2; mi++) {
                int row = wm * 32 + mi * 16 + (lane & 15);
                int gg = (kb >> 3) + (lane >> 4);
                uint32_t aad = (uint32_t)(row * 64 + ((gg ^ ((row >> 1) & 3)) << 4));
                uint32_t ah0, ah1, ah2, ah3, al0, al1, al2, al3;
                ldsm_x4(ah0, ah1, ah2, ah3, st + aad);
                ldsm_x4(al0, al1, al2, al3, st + 8192 + aad);
#pragma unroll
                for (int ni = 0; ni < 4; ni++) {
                    mma16816(acc[mi][ni], ah0, ah1, ah2, ah3, bh[ni][0], bh[ni][1]);
                    mma16816(acc[mi][ni], ah0, ah1, ah2, ah3, bl[ni][0], bl[ni][1]);
                    mma16816(acc[mi][ni], al0, al1, al2, al3, bh[ni][0], bh[ni][1]);
                }
            }
        }
        __syncthreads();
    }
#undef G_LOAD

    int g = lane >> 2, tg = lane & 3;
#pragma unroll
    for (int mi = 0; mi < 2; mi++) {
#pragma unroll
        for (int ni = 0; ni < 4; ni++) {
            int r0 = m0 + wm * 32 + mi * 16 + g;
            int c0 = n0 + wn * 32 + ni * 8 + tg * 2;
#pragma unroll
            for (int h = 0; h < 2; h++) {
                int r = r0 + h * 8;
                float v0 = acc[mi][ni][h * 2 + 0];
                float v1 = acc[mi][ni][h * 2 + 1];
                if (mode == 0) { v0 += bias[c0]; v1 += bias[c0 + 1]; }
                else {
                    v0 = 1.0f / (1.0f + expf(-v0));
                    v1 = 1.0f / (1.0f + expf(-v1));
                }
                *(float2*)&C[(size_t)r * N + c0] = make_float2(v0, v1);
            }
        }
    }
}

// ---------------- pipelined recurrence step (unchanged from R8) ----------------
#define STEP_SMEM 49152

__global__ void __launch_bounds__(256, 1) mma_step2(const __nv_bfloat16* __restrict__ Whh,
                                                    const __nv_bfloat16* __restrict__ Whl,
                                                    const __nv_bfloat16* __restrict__ hh,
                                                    const __nv_bfloat16* __restrict__ hl,
                                                    const float* __restrict__ xwx_t,
                                                    const float* __restrict__ gate_t,
                                                    const float* __restrict__ z_t,
                                                    float* __restrict__ hnext_f,
                                                    __nv_bfloat16* __restrict__ hh_n,
                                                    __nv_bfloat16* __restrict__ hl_n,
                                                    float* __restrict__ out_t,
                                                    const float* __restrict__ scale) {
    extern __shared__ char smem[];
    uint32_t sb = smem_u32(smem);
    int t = threadIdx.x;
    int wid = t >> 5, lane = t & 31;
    int wm = wid & 3, wn = wid >> 2;
    int e0 = blockIdx.x * 32;

    float acc[2][4];
#pragma unroll
    for (int ni = 0; ni < 2; ni++)
#pragma unroll
        for (int j = 0; j < 4; j++) acc[ni][j] = 0.0f;

    const int rh0 = t >> 3, gh0 = t & 7;
    const int rh1 = (t + 256) >> 3;
    uint32_t hoff0 = (uint32_t)(rh0 * 128 + ((gh0 ^ (rh0 & 7)) << 4));
    uint32_t hoff1 = (uint32_t)(rh1 * 128 + ((gh0 ^ (rh1 & 7)) << 4));
    const int rw0 = t >> 3, gw0 = t & 7;
    uint32_t woff0 = (uint32_t)(rw0 * 128 + ((gw0 ^ (rw0 & 7)) << 4));

#define S_LOAD(s, kt)  do {                                                               \
        int k0 = (kt) * 64;                                                               \
        uint32_t st = sb + (s) * 24576;                                                   \
        cp16(st + hoff0,         &hh[rh0 * D_SZ + k0 + gh0 * 8]);                         \
        cp16(st + hoff1,         &hh[rh1 * D_SZ + k0 + gh0 * 8]);                         \
        cp16(st + 8192 + hoff0,  &hl[rh0 * D_SZ + k0 + gh0 * 8]);                         \
        cp16(st + 8192 + hoff1,  &hl[rh1 * D_SZ + k0 + gh0 * 8]);                         \
        cp16(st + 16384 + woff0, &Whh[(size_t)(e0 + rw0) * D_SZ + k0 + gw0 * 8]);         \
        cp16(st + 20480 + woff0, &Whl[(size_t)(e0 + rw0) * D_SZ + k0 + gw0 * 8]);         \
        cp_commit();                                                                      \
    } while (0)

    S_LOAD(0, 0);

    const int NKT = D_SZ / 64;  // 32
    for (int kt = 0; kt < NKT; kt++) {
        int s = kt & 1;
        if (kt < NKT - 1) {
            S_LOAD(s ^ 1, kt + 1);
            cp_wait<1>();
        } else {
            cp_wait<0>();
        }
        __syncthreads();
        uint32_t st = sb + s * 24576;
#pragma unroll
        for (int ks = 0; ks < 4; ks++) {
            int kb = ks * 16;
            uint32_t ah0, ah1, ah2, ah3, al0, al1, al2, al3;
            {
                int row = wm * 16 + (lane & 15);
                int gg = (kb >> 3) + (lane >> 4);
                uint32_t aad = (uint32_t)(row * 128 + ((gg ^ (row & 7)) << 4));
                ldsm_x4(ah0, ah1, ah2, ah3, st + aad);
                ldsm_x4(al0, al1, al2, al3, st + 8192 + aad);
            }
            uint32_t bh[2][2], bl[2][2];
            {
                int nrow = wn * 16 + ((lane >> 4) << 3) + (lane & 7);
                int gg = (kb >> 3) + ((lane >> 3) & 1);
                uint32_t bad = (uint32_t)(nrow * 128 + ((gg ^ (nrow & 7)) << 4));
                ldsm_x4(bh[0][0], bh[0][1], bh[1][0], bh[1][1], st + 16384 + bad);
                ldsm_x4(bl[0][0], bl[0][1], bl[1][0], bl[1][1], st + 20480 + bad);
            }
#pragma unroll
            for (int ni = 0; ni < 2; ni++) {
                mma16816(acc[ni], ah0, ah1, ah2, ah3, bh[ni][0], bh[ni][1]);
                mma16816(acc[ni], ah0, ah1, ah2, ah3, bl[ni][0], bl[ni][1]);
                mma16816(acc[ni], al0, al1, al2, al3, bh[ni][0], bh[ni][1]);
            }
        }
        __syncthreads();
    }
#undef S_LOAD

    float s = scale[0];
    int g = lane >> 2, tg = lane & 3;
#pragma unroll
    for (int ni = 0; ni < 2; ni++) {
#pragma unroll
        for (int h = 0; h < 2; h++) {
            int b = wm * 16 + g + h * 8;
            int e = e0 + wn * 16 + ni * 8 + tg * 2;
            int idx = b * D_SZ + e;
#pragma unroll
            for (int j = 0; j < 2; j++) {
                float Rh = acc[ni][h * 2 + j] * s;
                float gg = gate_t[idx + j];
                float pre = xwx_t[idx + j] + Rh * gg;
                float hv = tanhf(pre);
                hnext_f[idx + j] = hv;
                __nv_bfloat16 hb = __float2bfloat16(hv);
                hh_n[idx + j] = hb;
                hl_n[idx + j] = __float2bfloat16(hv - __bfloat162float(hb));
                float zz = z_t[idx + j];
                out_t[idx + j] = hv * (zz / (1.0f + expf(-zz)));
            }
        }
    }
}

// ---------------- launch ----------------
extern "C" void kernel_launch(void* const* d_in, const int* in_sizes, int n_in,
                              void* d_out, int out_size) {
    const float* x    = (const float*)d_in[0];
    const float* z    = (const float*)d_in[1];
    const float* h0   = (const float*)d_in[2];
    const float* Wx   = (const float*)d_in[3];
    const float* Wh   = (const float*)d_in[4];
    const float* Wg   = (const float*)d_in[5];
    const float* bias = (const float*)d_in[6];
    float* out = (float*)d_out;

    float *p_u, *p_v, *p_w, *p_scale, *p_xwx, *p_gate, *p_hbuf;
    cudaGetSymbolAddress((void**)&p_u, g_u);
    cudaGetSymbolAddress((void**)&p_v, g_v);
    cudaGetSymbolAddress((void**)&p_w, g_w);
    cudaGetSymbolAddress((void**)&p_scale, g_scale);
    cudaGetSymbolAddress((void**)&p_xwx, g_xwx);
    cudaGetSymbolAddress((void**)&p_gate, g_gate);
    cudaGetSymbolAddress((void**)&p_hbuf, g_hbuf);

    __nv_bfloat16 *p_xhi, *p_xlo, *p_wxhi, *p_wxlo, *p_wghi, *p_wglo, *p_whhi, *p_whlo;
    __nv_bfloat16 *p_hhi, *p_hlo;
    cudaGetSymbolAddress((void**)&p_xhi, gx_hi);
    cudaGetSymbolAddress((void**)&p_xlo, gx_lo);
    cudaGetSymbolAddress((void**)&p_wxhi, gwx_hi);
    cudaGetSymbolAddress((void**)&p_wxlo, gwx_lo);
    cudaGetSymbolAddress((void**)&p_wghi, gwg_hi);
    cudaGetSymbolAddress((void**)&p_wglo, gwg_lo);
    cudaGetSymbolAddress((void**)&p_whhi, gwh_hi);
    cudaGetSymbolAddress((void**)&p_whlo, gwh_lo);
    cudaGetSymbolAddress((void**)&p_hhi, gh_hi);
    cudaGetSymbolAddress((void**)&p_hlo, gh_lo);

    cudaFuncSetAttribute(mma_gemm3, cudaFuncAttributeMaxDynamicSharedMemorySize, GEMM_SMEM);
    cudaFuncSetAttribute(mma_step2, cudaFuncAttributeMaxDynamicSharedMemorySize, STEP_SMEM);

    long long need = (long long)TBD + (long long)(T_STEPS + 1) * BD;
    float* out_h = ((long long)out_size >= need) ? (out + TBD) : p_hbuf;

    dim3 gg(D_SZ / 64, (T_STEPS * B_SZ) / 128);  // (32, 128) = 4096 CTAs

    // --- ordered so launch #4 = mma_gemm3 (ncu capture window) ---
    k_split<<<TBD / 4 / 256, 256>>>(x, p_xhi, p_xlo);                 // 1
    k_split<<<DD / 4 / 256, 256>>>(Wx, p_wxhi, p_wxlo);               // 2
    k_split<<<DD / 4 / 256, 256>>>(Wg, p_wghi, p_wglo);               // 3
    mma_gemm3<<<gg, 256, GEMM_SMEM>>>(p_xhi, p_xlo, p_wxhi, p_wxlo,   // 4 (profiled)
                                      bias, p_xwx, 0);
    k_split<<<DD / 4 / 256, 256>>>(Wh, p_whhi, p_whlo);
    k_split<<<BD / 4 / 256, 256>>>(h0, p_hhi, p_hlo);

    // --- spectral norm of W_h (fp32) ---
    k_init_u<<<1, 1024>>>(p_u);
    for (int it = 0; it < 3; it++) {
        k_mvT<<<16, 256>>>(Wh, p_u, p_v);
        k_norm<<<1, 1024>>>(p_v);
        k_mv<<<256, 256>>>(Wh, p_v, p_u);
        k_norm<<<1, 1024>>>(p_u);
    }
    k_mv<<<256, 256>>>(Wh, p_v, p_w);
    k_sigma<<<1, 1024>>>(p_u, p_w, p_scale);

    // --- second projection ---
    mma_gemm3<<<gg, 256, GEMM_SMEM>>>(p_xhi, p_xlo, p_wghi, p_wglo, bias, p_gate, 1);

    // h[0] = h0
    cudaMemcpyAsync(out_h, h0, (size_t)BD * sizeof(float), cudaMemcpyDeviceToDevice);

    // --- sequential recurrence ---
    for (int t = 0; t < T_STEPS; t++) {
        int cur = t & 1, nxt = cur ^ 1;
        mma_step2<<<64, 256, STEP_SMEM>>>(p_whhi, p_whlo,
                                          p_hhi + (size_t)cur * BD, p_hlo + (size_t)cur * BD,
                                          p_xwx + (size_t)t * BD,
                                          p_gate + (size_t)t * BD,
                                          z + (size_t)t * BD,
                                          out_h + (size_t)(t + 1) * BD,
                                          p_hhi + (size_t)nxt * BD, p_hlo + (size_t)nxt * BD,
                                          out + (size_t)t * BD,
                                          p_scale);
    }
}

// round 11
// speedup vs baseline: 4.0677x; 1.1562x over previous
#include <cuda_runtime.h>
#include <cuda_bf16.h>
#include <math.h>
#include <stdint.h>

#define T_STEPS 256
#define B_SZ 64
#define D_SZ 2048
#define BD (B_SZ * D_SZ)                 // 131072
#define TBD (T_STEPS * BD)               // 33554432
#define DD (D_SZ * D_SZ)                 // 4194304

// ---------------- device scratch (no allocations allowed) ----------------
__device__ float g_xwx[TBD];
__device__ float g_gate[TBD];
__device__ float g_hbuf[(T_STEPS + 1) * BD];
__device__ float g_u[D_SZ];
__device__ float g_v[D_SZ];
__device__ float g_w[D_SZ];
__device__ float g_scale;

__device__ __nv_bfloat16 gx_hi[TBD], gx_lo[TBD];
__device__ __nv_bfloat16 gwx_hi[DD], gwx_lo[DD];
__device__ __nv_bfloat16 gwg_hi[DD], gwg_lo[DD];
__device__ __nv_bfloat16 gwh_hi[DD], gwh_lo[DD];
__device__ __nv_bfloat16 gh_hi[2][BD], gh_lo[2][BD];

// ---------------- threefry2x32 (JAX partitionable mode) ----------------
__device__ __forceinline__ uint32_t rotl32(uint32_t x, int n) {
    return (x << n) | (x >> (32 - n));
}
#define TF_ROUND(x0, x1, r) do { x0 += x1; x1 = rotl32(x1, r); x1 ^= x0; } while (0)
#define TF_G_A(x0, x1) do { TF_ROUND(x0,x1,13); TF_ROUND(x0,x1,15); TF_ROUND(x0,x1,26); TF_ROUND(x0,x1,6); } while (0)
#define TF_G_B(x0, x1) do { TF_ROUND(x0,x1,17); TF_ROUND(x0,x1,29); TF_ROUND(x0,x1,16); TF_ROUND(x0,x1,24); } while (0)

__device__ __forceinline__ uint32_t threefry_part_bits(uint32_t cnt_hi, uint32_t cnt_lo) {
    const uint32_t ks0 = 0u, ks1 = 42u;
    const uint32_t ks2 = 0x1BD11BDAu ^ ks0 ^ ks1;
    uint32_t x0 = cnt_hi + ks0;
    uint32_t x1 = cnt_lo + ks1;
    TF_G_A(x0, x1); x0 += ks1; x1 += ks2 + 1u;
    TF_G_B(x0, x1); x0 += ks2; x1 += ks0 + 2u;
    TF_G_A(x0, x1); x0 += ks0; x1 += ks1 + 3u;
    TF_G_B(x0, x1); x0 += ks1; x1 += ks2 + 4u;
    TF_G_A(x0, x1); x0 += ks2; x1 += ks0 + 5u;
    return x0 ^ x1;
}

__device__ __forceinline__ float bits_to_normal(uint32_t bits) {
    float f = __uint_as_float((bits >> 9) | 0x3f800000u) - 1.0f;
    const float lo = -0.99999994f;
    const float span = 2.0f;
    float u = fmaf(f, span, lo);
    u = fmaxf(lo, u);
    return 1.41421356237f * erfinvf(u);
}

__global__ void k_init_u(float* __restrict__ u_out) {
    __shared__ float red[1024];
    __shared__ float inv;
    int i = threadIdx.x;
    float n0 = bits_to_normal(threefry_part_bits(0u, (uint32_t)i));
    float n1 = bits_to_normal(threefry_part_bits(0u, (uint32_t)(i + 1024)));
    red[i] = n0 * n0 + n1 * n1;
    __syncthreads();
    for (int s = 512; s > 0; s >>= 1) {
        if (i < s) red[i] += red[i + s];
        __syncthreads();
    }
    if (i == 0) inv = 1.0f / sqrtf(red[0]);
    __syncthreads();
    u_out[i] = n0 * inv;
    u_out[i + 1024] = n1 * inv;
}

__global__ void __launch_bounds__(256) k_mvT(const float* __restrict__ W,
                                             const float* __restrict__ u,
                                             float* __restrict__ v) {
    __shared__ float part[2][128];
    int t = threadIdx.x;
    int jl = t & 127, half = t >> 7;
    int j = blockIdx.x * 128 + jl;
    int i0 = half * 1024;
    float s = 0.0f;
#pragma unroll 8
    for (int i = 0; i < 1024; i++)
        s = fmaf(W[(size_t)(i0 + i) * D_SZ + j], u[i0 + i], s);
    part[half][jl] = s;
    __syncthreads();
    if (t < 128) v[blockIdx.x * 128 + t] = part[0][t] + part[1][t];
}

__global__ void __launch_bounds__(256) k_mv(const float* __restrict__ W,
                                            const float* __restrict__ v,
                                            float* __restrict__ o) {
    int gw = (blockIdx.x * blockDim.x + threadIdx.x) >> 5;
    int lane = threadIdx.x & 31;
    const float* row = W + (size_t)gw * D_SZ;
    float s = 0.0f;
#pragma unroll 8
    for (int k = lane; k < D_SZ; k += 32) s = fmaf(row[k], v[k], s);
#pragma unroll
    for (int off = 16; off > 0; off >>= 1)
        s += __shfl_xor_sync(0xffffffffu, s, off);
    if (lane == 0) o[gw] = s;
}

__global__ void k_norm(float* __restrict__ v) {
    __shared__ float red[1024];
    __shared__ float inv;
    int i = threadIdx.x;
    float a = v[i], b = v[i + 1024];
    red[i] = a * a + b * b;
    __syncthreads();
    for (int s = 512; s > 0; s >>= 1) {
        if (i < s) red[i] += red[i + s];
        __syncthreads();
    }
    if (i == 0) inv = 1.0f / (sqrtf(red[0]) + 1e-8f);
    __syncthreads();
    v[i] = a * inv;
    v[i + 1024] = b * inv;
}

__global__ void k_sigma(const float* __restrict__ u, const float* __restrict__ w,
                        float* __restrict__ scale) {
    __shared__ float red[1024];
    int i = threadIdx.x;
    red[i] = u[i] * w[i] + u[i + 1024] * w[i + 1024];
    __syncthreads();
    for (int s = 512; s > 0; s >>= 1) {
        if (i < s) red[i] += red[i + s];
        __syncthreads();
    }
    if (i == 0) scale[0] = 0.99f / (fabsf(red[0]) + 1e-8f);
}

// ---------------- fp32 -> (hi, lo) bf16 split ----------------
__global__ void __launch_bounds__(256) k_split(const float* __restrict__ src,
                                               __nv_bfloat16* __restrict__ hi,
                                               __nv_bfloat16* __restrict__ lo) {
    int i = blockIdx.x * blockDim.x + threadIdx.x;
    float4 v = ((const float4*)src)[i];
    union { __nv_bfloat16 b[4]; uint2 u; } ph, pl;
    float vv[4] = {v.x, v.y, v.z, v.w};
#pragma unroll
    for (int j = 0; j < 4; j++) {
        __nv_bfloat16 h = __float2bfloat16(vv[j]);
        ph.b[j] = h;
        pl.b[j] = __float2bfloat16(vv[j] - __bfloat162float(h));
    }
    ((uint2*)hi)[i] = ph.u;
    ((uint2*)lo)[i] = pl.u;
}

// ---------------- async copy + ldmatrix helpers ----------------
__device__ __forceinline__ uint32_t smem_u32(const void* p) {
    uint32_t a;
    asm("{ .reg .u64 t; cvta.to.shared.u64 t, %1; cvt.u32.u64 %0, t; }" : "=r"(a) : "l"(p));
    return a;
}
__device__ __forceinline__ void cp16(uint32_t dst, const void* src) {
    asm volatile("cp.async.cg.shared.global [%0], [%1], 16;" :: "r"(dst), "l"(src));
}
__device__ __forceinline__ void cp_commit() {
    asm volatile("cp.async.commit_group;" ::: "memory");
}
template <int N> __device__ __forceinline__ void cp_wait() {
    asm volatile("cp.async.wait_group %0;" :: "n"(N) : "memory");
}
__device__ __forceinline__ void ldsm_x4(uint32_t& r0, uint32_t& r1, uint32_t& r2, uint32_t& r3,
                                        uint32_t addr) {
    asm volatile("ldmatrix.sync.aligned.m8n8.x4.shared.b16 {%0,%1,%2,%3}, [%4];"
                 : "=r"(r0), "=r"(r1), "=r"(r2), "=r"(r3) : "r"(addr));
}
__device__ __forceinline__ void mma16816(float* c,
                                         uint32_t a0, uint32_t a1, uint32_t a2, uint32_t a3,
                                         uint32_t b0, uint32_t b1) {
    asm volatile(
        "mma.sync.aligned.m16n8k16.row.col.f32.bf16.bf16.f32 "
        "{%0,%1,%2,%3}, {%4,%5,%6,%7}, {%8,%9}, {%0,%1,%2,%3};\n"
        : "+f"(c[0]), "+f"(c[1]), "+f"(c[2]), "+f"(c[3])
        : "r"(a0), "r"(a1), "r"(a2), "r"(a3), "r"(b0), "r"(b1));
}

// ---------------- pipelined HMMA GEMM, tile 128x64, 2 CTAs/SM (unchanged R9) --------
#define GEMM_SMEM 49152

__global__ void __launch_bounds__(256, 2) mma_gemm3(const __nv_bfloat16* __restrict__ Ah,
                                                    const __nv_bfloat16* __restrict__ Al,
                                                    const __nv_bfloat16* __restrict__ Bh,
                                                    const __nv_bfloat16* __restrict__ Bl,
                                                    const float* __restrict__ bias,
                                                    float* __restrict__ C,
                                                    int mode) {
    extern __shared__ char smem[];
    uint32_t sb = smem_u32(smem);
    const int K = D_SZ, N = D_SZ;
    int t = threadIdx.x;
    int wid = t >> 5, lane = t & 31;
    int wm = wid >> 1, wn = wid & 1;
    int m0 = blockIdx.y * 128, n0 = blockIdx.x * 64;

    float acc[2][4][4];
#pragma unroll
    for (int mi = 0; mi < 2; mi++)
#pragma unroll
        for (int ni = 0; ni < 4; ni++)
#pragma unroll
            for (int j = 0; j < 4; j++) acc[mi][ni][j] = 0.0f;

    const int ra0 = t >> 2, ga = t & 3;
    const int ra1 = (t + 256) >> 2;
    uint32_t aoff0 = (uint32_t)(ra0 * 64 + ((ga ^ ((ra0 >> 1) & 3)) << 4));
    uint32_t aoff1 = (uint32_t)(ra1 * 64 + ((ga ^ ((ra1 >> 1) & 3)) << 4));
    const int rb0 = t >> 2;
    uint32_t boff0 = (uint32_t)(rb0 * 64 + ((ga ^ ((rb0 >> 1) & 3)) << 4));

#define G_LOAD(s, kt)  do {                                                              \
        int k0 = (kt) * 32;                                                              \
        uint32_t st = sb + (s) * 24576;                                                  \
        cp16(st + aoff0,         &Ah[(size_t)(m0 + ra0) * K + k0 + ga * 8]);             \
        cp16(st + aoff1,         &Ah[(size_t)(m0 + ra1) * K + k0 + ga * 8]);             \
        cp16(st + 8192 + aoff0,  &Al[(size_t)(m0 + ra0) * K + k0 + ga * 8]);             \
        cp16(st + 8192 + aoff1,  &Al[(size_t)(m0 + ra1) * K + k0 + ga * 8]);             \
        cp16(st + 16384 + boff0, &Bh[(size_t)(n0 + rb0) * K + k0 + ga * 8]);             \
        cp16(st + 20480 + boff0, &Bl[(size_t)(n0 + rb0) * K + k0 + ga * 8]);             \
        cp_commit();                                                                     \
    } while (0)

    G_LOAD(0, 0);

    const int NKT = K / 32;
    for (int kt = 0; kt < NKT; kt++) {
        int s = kt & 1;
        if (kt < NKT - 1) {
            G_LOAD(s ^ 1, kt + 1);
            cp_wait<1>();
        } else {
            cp_wait<0>();
        }
        __syncthreads();
        uint32_t st = sb + s * 24576;
#pragma unroll
        for (int ks = 0; ks < 2; ks++) {
            int kb = ks * 16;
            uint32_t bh[4][2], bl[4][2];
            {
                int nrow = wn * 32 + ((lane >> 4) << 3) + (lane & 7);
                int gg = (kb >> 3) + ((lane >> 3) & 1);
                uint32_t a0 = (uint32_t)(nrow * 64 + ((gg ^ ((nrow >> 1) & 3)) << 4));
                int nrow2 = nrow + 16;
                uint32_t a1 = (uint32_t)(nrow2 * 64 + ((gg ^ ((nrow2 >> 1) & 3)) << 4));
                ldsm_x4(bh[0][0], bh[0][1], bh[1][0], bh[1][1], st + 16384 + a0);
                ldsm_x4(bh[2][0], bh[2][1], bh[3][0], bh[3][1], st + 16384 + a1);
                ldsm_x4(bl[0][0], bl[0][1], bl[1][0], bl[1][1], st + 20480 + a0);
                ldsm_x4(bl[2][0], bl[2][1], bl[3][0], bl[3][1], st + 20480 + a1);
            }
#pragma unroll
            for (int mi = 0; mi < 2; mi++) {
                int row = wm * 32 + mi * 16 + (lane & 15);
                int gg = (kb >> 3) + (lane >> 4);
                uint32_t aad = (uint32_t)(row * 64 + ((gg ^ ((row >> 1) & 3)) << 4));
                uint32_t ah0, ah1, ah2, ah3, al0, al1, al2, al3;
                ldsm_x4(ah0, ah1, ah2, ah3, st + aad);
                ldsm_x4(al0, al1, al2, al3, st + 8192 + aad);
#pragma unroll
                for (int ni = 0; ni < 4; ni++) {
                    mma16816(acc[mi][ni], ah0, ah1, ah2, ah3, bh[ni][0], bh[ni][1]);
                    mma16816(acc[mi][ni], ah0, ah1, ah2, ah3, bl[ni][0], bl[ni][1]);
                    mma16816(acc[mi][ni], al0, al1, al2, al3, bh[ni][0], bh[ni][1]);
                }
            }
        }
        __syncthreads();
    }
#undef G_LOAD

    int g = lane >> 2, tg = lane & 3;
#pragma unroll
    for (int mi = 0; mi < 2; mi++) {
#pragma unroll
        for (int ni = 0; ni < 4; ni++) {
            int r0 = m0 + wm * 32 + mi * 16 + g;
            int c0 = n0 + wn * 32 + ni * 8 + tg * 2;
#pragma unroll
            for (int h = 0; h < 2; h++) {
                int r = r0 + h * 8;
                float v0 = acc[mi][ni][h * 2 + 0];
                float v1 = acc[mi][ni][h * 2 + 1];
                if (mode == 0) { v0 += bias[c0]; v1 += bias[c0 + 1]; }
                else {
                    v0 = 1.0f / (1.0f + expf(-v0));
                    v1 = 1.0f / (1.0f + expf(-v1));
                }
                *(float2*)&C[(size_t)r * N + c0] = make_float2(v0, v1);
            }
        }
    }
}

// ---------------- recurrence step: 16 features/CTA, 128 CTAs ----------------
// 256 thr, 8 warps: wm=wid&3 (16 batch rows), wn=wid>>2 (8 feats). BK=64, 2-stage.
// Stage: Hh 8K, Hl 8K, Whh 2K, Whl 2K = 20480B; 2 stages = 40960B dynamic.
#define STEP_STAGE 20480
#define STEP_SMEM (2 * STEP_STAGE)

__global__ void __launch_bounds__(256, 1) mma_step3(const __nv_bfloat16* __restrict__ Whh,
                                                    const __nv_bfloat16* __restrict__ Whl,
                                                    const __nv_bfloat16* __restrict__ hh,
                                                    const __nv_bfloat16* __restrict__ hl,
                                                    const float* __restrict__ xwx_t,
                                                    const float* __restrict__ gate_t,
                                                    const float* __restrict__ z_t,
                                                    float* __restrict__ hnext_f,
                                                    __nv_bfloat16* __restrict__ hh_n,
                                                    __nv_bfloat16* __restrict__ hl_n,
                                                    float* __restrict__ out_t,
                                                    const float* __restrict__ scale) {
    extern __shared__ char smem[];
    uint32_t sb = smem_u32(smem);
    int t = threadIdx.x;
    int wid = t >> 5, lane = t & 31;
    int wm = wid & 3, wn = wid >> 2;     // warp tile: 16 batch x 8 feats
    int e0 = blockIdx.x * 16;

    float acc[4] = {0.f, 0.f, 0.f, 0.f};

    const int rh0 = t >> 3, gh0 = t & 7;
    const int rh1 = (t + 256) >> 3;
    uint32_t hoff0 = (uint32_t)(rh0 * 128 + ((gh0 ^ (rh0 & 7)) << 4));
    uint32_t hoff1 = (uint32_t)(rh1 * 128 + ((gh0 ^ (rh1 & 7)) << 4));
    const int rw0 = t >> 3, gw0 = t & 7;  // W: rows 0..15 need t<128
    uint32_t woff0 = (uint32_t)(rw0 * 128 + ((gw0 ^ (rw0 & 7)) << 4));

#define S_LOAD(s, kt)  do {                                                               \
        int k0 = (kt) * 64;                                                               \
        uint32_t st = sb + (s) * STEP_STAGE;                                              \
        cp16(st + hoff0,        &hh[rh0 * D_SZ + k0 + gh0 * 8]);                          \
        cp16(st + hoff1,        &hh[rh1 * D_SZ + k0 + gh0 * 8]);                          \
        cp16(st + 8192 + hoff0, &hl[rh0 * D_SZ + k0 + gh0 * 8]);                          \
        cp16(st + 8192 + hoff1, &hl[rh1 * D_SZ + k0 + gh0 * 8]);                          \
        if (t < 128) {                                                                    \
            cp16(st + 16384 + woff0, &Whh[(size_t)(e0 + rw0) * D_SZ + k0 + gw0 * 8]);     \
            cp16(st + 18432 + woff0, &Whl[(size_t)(e0 + rw0) * D_SZ + k0 + gw0 * 8]);     \
        }                                                                                 \
        cp_commit();                                                                      \
    } while (0)

    S_LOAD(0, 0);

    const int NKT = D_SZ / 64;  // 32
    for (int kt = 0; kt < NKT; kt++) {
        int s = kt & 1;
        if (kt < NKT - 1) {
            S_LOAD(s ^ 1, kt + 1);
            cp_wait<1>();
        } else {
            cp_wait<0>();
        }
        __syncthreads();
        uint32_t st = sb + s * STEP_STAGE;
#pragma unroll
        for (int kh = 0; kh < 2; kh++) {       // k32 halves of the k64 stage
            // B fragments: one ldsm.x4 (hi/lo) covers 8 feats x k32 (4 matrices)
            uint32_t bh4[4], bl4[4];
            {
                int nrow = wn * 8 + (lane & 7);
                int gg = kh * 4 + (lane >> 3);   // 4 k-chunks of 8 elems
                uint32_t bad = (uint32_t)(nrow * 128 + ((gg ^ (nrow & 7)) << 4));
                ldsm_x4(bh4[0], bh4[1], bh4[2], bh4[3], st + 16384 + bad);
                ldsm_x4(bl4[0], bl4[1], bl4[2], bl4[3], st + 18432 + bad);
            }
#pragma unroll
            for (int q = 0; q < 2; q++) {      // k16 steps within k32
                int kb = kh * 32 + q * 16;
                uint32_t ah0, ah1, ah2, ah3, al0, al1, al2, al3;
                {
                    int row = wm * 16 + (lane & 15);
                    int gg = (kb >> 3) + (lane >> 4);
                    uint32_t aad = (uint32_t)(row * 128 + ((gg ^ (row & 7)) << 4));
                    ldsm_x4(ah0, ah1, ah2, ah3, st + aad);
                    ldsm_x4(al0, al1, al2, al3, st + 8192 + aad);
                }
                mma16816(acc, ah0, ah1, ah2, ah3, bh4[q * 2], bh4[q * 2 + 1]);
                mma16816(acc, ah0, ah1, ah2, ah3, bl4[q * 2], bl4[q * 2 + 1]);
                mma16816(acc, al0, al1, al2, al3, bh4[q * 2], bh4[q * 2 + 1]);
            }
        }
        __syncthreads();
    }
#undef S_LOAD

    float s = scale[0];
    int g = lane >> 2, tg = lane & 3;
#pragma unroll
    for (int h = 0; h < 2; h++) {
        int b = wm * 16 + g + h * 8;
        int e = e0 + wn * 8 + tg * 2;
        int idx = b * D_SZ + e;
#pragma unroll
        for (int j = 0; j < 2; j++) {
            float Rh = acc[h * 2 + j] * s;
            float gg = gate_t[idx + j];
            float pre = xwx_t[idx + j] + Rh * gg;
            float hv = tanhf(pre);
            hnext_f[idx + j] = hv;
            __nv_bfloat16 hb = __float2bfloat16(hv);
            hh_n[idx + j] = hb;
            hl_n[idx + j] = __float2bfloat16(hv - __bfloat162float(hb));
            float zz = z_t[idx + j];
            out_t[idx + j] = hv * (zz / (1.0f + expf(-zz)));
        }
    }
}

// ---------------- launch ----------------
extern "C" void kernel_launch(void* const* d_in, const int* in_sizes, int n_in,
                              void* d_out, int out_size) {
    const float* x    = (const float*)d_in[0];
    const float* z    = (const float*)d_in[1];
    const float* h0   = (const float*)d_in[2];
    const float* Wx   = (const float*)d_in[3];
    const float* Wh   = (const float*)d_in[4];
    const float* Wg   = (const float*)d_in[5];
    const float* bias = (const float*)d_in[6];
    float* out = (float*)d_out;

    float *p_u, *p_v, *p_w, *p_scale, *p_xwx, *p_gate, *p_hbuf;
    cudaGetSymbolAddress((void**)&p_u, g_u);
    cudaGetSymbolAddress((void**)&p_v, g_v);
    cudaGetSymbolAddress((void**)&p_w, g_w);
    cudaGetSymbolAddress((void**)&p_scale, g_scale);
    cudaGetSymbolAddress((void**)&p_xwx, g_xwx);
    cudaGetSymbolAddress((void**)&p_gate, g_gate);
    cudaGetSymbolAddress((void**)&p_hbuf, g_hbuf);

    __nv_bfloat16 *p_xhi, *p_xlo, *p_wxhi, *p_wxlo, *p_wghi, *p_wglo, *p_whhi, *p_whlo;
    __nv_bfloat16 *p_hhi, *p_hlo;
    cudaGetSymbolAddress((void**)&p_xhi, gx_hi);
    cudaGetSymbolAddress((void**)&p_xlo, gx_lo);
    cudaGetSymbolAddress((void**)&p_wxhi, gwx_hi);
    cudaGetSymbolAddress((void**)&p_wxlo, gwx_lo);
    cudaGetSymbolAddress((void**)&p_wghi, gwg_hi);
    cudaGetSymbolAddress((void**)&p_wglo, gwg_lo);
    cudaGetSymbolAddress((void**)&p_whhi, gwh_hi);
    cudaGetSymbolAddress((void**)&p_whlo, gwh_lo);
    cudaGetSymbolAddress((void**)&p_hhi, gh_hi);
    cudaGetSymbolAddress((void**)&p_hlo, gh_lo);

    cudaFuncSetAttribute(mma_gemm3, cudaFuncAttributeMaxDynamicSharedMemorySize, GEMM_SMEM);
    cudaFuncSetAttribute(mma_step3, cudaFuncAttributeMaxDynamicSharedMemorySize, STEP_SMEM);

    long long need = (long long)TBD + (long long)(T_STEPS + 1) * BD;
    float* out_h = ((long long)out_size >= need) ? (out + TBD) : p_hbuf;

    dim3 gg(D_SZ / 64, (T_STEPS * B_SZ) / 128);  // (32, 128)

    // launch #4 = mma_gemm3 (ncu capture window; unchanged control)
    k_split<<<TBD / 4 / 256, 256>>>(x, p_xhi, p_xlo);                 // 1
    k_split<<<DD / 4 / 256, 256>>>(Wx, p_wxhi, p_wxlo);               // 2
    k_split<<<DD / 4 / 256, 256>>>(Wg, p_wghi, p_wglo);               // 3
    mma_gemm3<<<gg, 256, GEMM_SMEM>>>(p_xhi, p_xlo, p_wxhi, p_wxlo,   // 4 (profiled)
                                      bias, p_xwx, 0);
    k_split<<<DD / 4 / 256, 256>>>(Wh, p_whhi, p_whlo);
    k_split<<<BD / 4 / 256, 256>>>(h0, p_hhi, p_hlo);

    // --- spectral norm of W_h (fp32) ---
    k_init_u<<<1, 1024>>>(p_u);
    for (int it = 0; it < 3; it++) {
        k_mvT<<<16, 256>>>(Wh, p_u, p_v);
        k_norm<<<1, 1024>>>(p_v);
        k_mv<<<256, 256>>>(Wh, p_v, p_u);
        k_norm<<<1, 1024>>>(p_u);
    }
    k_mv<<<256, 256>>>(Wh, p_v, p_w);
    k_sigma<<<1, 1024>>>(p_u, p_w, p_scale);

    // --- second projection ---
    mma_gemm3<<<gg, 256, GEMM_SMEM>>>(p_xhi, p_xlo, p_wghi, p_wglo, bias, p_gate, 1);

    // h[0] = h0
    cudaMemcpyAsync(out_h, h0, (size_t)BD * sizeof(float), cudaMemcpyDeviceToDevice);

    // --- sequential recurrence (128 CTAs/step) ---
    for (int t = 0; t < T_STEPS; t++) {
        int cur = t & 1, nxt = cur ^ 1;
        mma_step3<<<D_SZ / 16, 256, STEP_SMEM>>>(p_whhi, p_whlo,
                                                 p_hhi + (size_t)cur * BD, p_hlo + (size_t)cur * BD,
                                                 p_xwx + (size_t)t * BD,
                                                 p_gate + (size_t)t * BD,
                                                 z + (size_t)t * BD,
                                                 out_h + (size_t)(t + 1) * BD,
                                                 p_hhi + (size_t)nxt * BD, p_hlo + (size_t)nxt * BD,
                                                 out + (size_t)t * BD,
                                                 p_scale);
    }
}